// round 1
// baseline (speedup 1.0000x reference)
#include <cuda_runtime.h>
#include <cstdint>

// Problem constants (fixed shapes from setup_inputs)
#define Bz   2
#define Cc   256
#define Hh   96
#define Ww   96
#define Oo   256
#define KK   9
#define Ho_  96
#define Wo_  96
#define Ss   (Ho_ * Wo_)      // 9216
#define CKk  (Cc * KK)        // 2304

// 170 MB scratch for the im2col buffer: col[b][c*9+k][s]
__device__ float g_col[(size_t)Bz * CKk * Ss];

// ---------------------------------------------------------------------------
// Stage 1: modulated deformable im2col
// One thread per (b, c, k, s); linear idx matches col layout exactly.
// ---------------------------------------------------------------------------
__global__ __launch_bounds__(256) void im2col_k(
    const float* __restrict__ inp,   // [B, C, H, W]
    const float* __restrict__ off,   // [B, 2K, H, W]
    const float* __restrict__ msk)   // [B, K, H, W]
{
    int idx = blockIdx.x * blockDim.x + threadIdx.x;
    const int total = Bz * Cc * KK * Ss;
    if (idx >= total) return;

    int s = idx % Ss;
    int t = idx / Ss;
    int k = t % KK;  t /= KK;
    int c = t % Cc;
    int b = t / Cc;

    int oh = s / Wo_;
    int ow = s - oh * Wo_;

    float dy = off[((size_t)(b * 2 * KK + 2 * k)) * Ss + s];
    float dx = off[((size_t)(b * 2 * KK + 2 * k + 1)) * Ss + s];
    float m  = msk[((size_t)(b * KK + k)) * Ss + s];

    float y = (float)(oh - 1 + (k / 3)) + dy;
    float x = (float)(ow - 1 + (k % 3)) + dx;

    float y0f = floorf(y);
    float x0f = floorf(x);
    float wy = y - y0f;
    float wx = x - x0f;
    int iy = (int)y0f;
    int ix = (int)x0f;

    const float* ip = inp + ((size_t)(b * Cc + c)) * (Hh * Ww);

    bool vy0 = (iy >= 0)     && (iy < Hh);
    bool vy1 = (iy + 1 >= 0) && (iy + 1 < Hh);
    bool vx0 = (ix >= 0)     && (ix < Ww);
    bool vx1 = (ix + 1 >= 0) && (ix + 1 < Ww);

    float v00 = (vy0 && vx0) ? ip[iy * Ww + ix]           : 0.0f;
    float v01 = (vy0 && vx1) ? ip[iy * Ww + ix + 1]       : 0.0f;
    float v10 = (vy1 && vx0) ? ip[(iy + 1) * Ww + ix]     : 0.0f;
    float v11 = (vy1 && vx1) ? ip[(iy + 1) * Ww + ix + 1] : 0.0f;

    float val = v00 * (1.0f - wy) * (1.0f - wx)
              + v01 * (1.0f - wy) * wx
              + v10 * wy * (1.0f - wx)
              + v11 * wy * wx;

    g_col[idx] = m * val;
}

// ---------------------------------------------------------------------------
// Stage 2: SGEMM  out[b][o][s] = sum_ck W[o][ck] * col[b][ck][s] + bias[o]
// M=256 (O), N=9216 (S), K=2304 (CK). All dims divide the tile sizes exactly.
// 128x128 block tile, BK=8, 256 threads, 8x8 per-thread micro-tile.
// ---------------------------------------------------------------------------
#define BM 128
#define BN 128
#define BK 8

__global__ __launch_bounds__(256) void sgemm_k(
    const float* __restrict__ Wt,    // [O, CK]
    const float* __restrict__ bias,  // [O]
    float* __restrict__ out)         // [B, O, S]
{
    const int b = blockIdx.z;
    const float* Bmat = g_col + (size_t)b * CKk * Ss;
    float* Cmat = out + (size_t)b * Oo * Ss;

    const int tileM = blockIdx.y * BM;
    const int tileN = blockIdx.x * BN;

    __shared__ float As[BK][BM];   // A transposed: As[k][m]
    __shared__ float Bs[BK][BN];

    const int tid = threadIdx.x;
    // A load: 128 rows x 8 cols = 256 float4
    const int aRow = tid >> 1;
    const int aCol = (tid & 1) * 4;
    // B load: 8 rows x 128 cols = 256 float4
    const int bRow = tid >> 5;
    const int bCol = (tid & 31) * 4;
    // compute mapping: 16x16 threads, 8x8 each
    const int tx = tid & 15;
    const int ty = tid >> 4;

    float acc[8][8];
#pragma unroll
    for (int i = 0; i < 8; i++)
#pragma unroll
        for (int j = 0; j < 8; j++) acc[i][j] = 0.0f;

    const float* Aptr = Wt + (size_t)(tileM + aRow) * CKk + aCol;
    const float* Bptr = Bmat + (size_t)bRow * Ss + tileN + bCol;

    for (int k0 = 0; k0 < CKk; k0 += BK) {
        float4 av = *(const float4*)(Aptr + k0);
        float4 bv = *(const float4*)(Bptr + (size_t)k0 * Ss);

        __syncthreads();   // previous tile fully consumed
        As[aCol + 0][aRow] = av.x;
        As[aCol + 1][aRow] = av.y;
        As[aCol + 2][aRow] = av.z;
        As[aCol + 3][aRow] = av.w;
        *(float4*)&Bs[bRow][bCol] = bv;
        __syncthreads();

#pragma unroll
        for (int kk = 0; kk < BK; kk++) {
            float a[8], bb[8];
#pragma unroll
            for (int i = 0; i < 8; i++) a[i] = As[kk][ty * 8 + i];
#pragma unroll
            for (int j = 0; j < 8; j++) bb[j] = Bs[kk][tx * 8 + j];
#pragma unroll
            for (int i = 0; i < 8; i++)
#pragma unroll
                for (int j = 0; j < 8; j++)
                    acc[i][j] = fmaf(a[i], bb[j], acc[i][j]);
        }
    }

#pragma unroll
    for (int i = 0; i < 8; i++) {
        const int row = tileM + ty * 8 + i;
        const float bv = bias[row];
        float* cp = Cmat + (size_t)row * Ss + tileN + tx * 8;
#pragma unroll
        for (int j = 0; j < 8; j += 4) {
            float4 v;
            v.x = acc[i][j + 0] + bv;
            v.y = acc[i][j + 1] + bv;
            v.z = acc[i][j + 2] + bv;
            v.w = acc[i][j + 3] + bv;
            *(float4*)(cp + j) = v;
        }
    }
}

// ---------------------------------------------------------------------------
extern "C" void kernel_launch(void* const* d_in, const int* in_sizes, int n_in,
                              void* d_out, int out_size)
{
    const float* inp  = (const float*)d_in[0];  // input  [2,256,96,96]
    const float* off  = (const float*)d_in[1];  // offset [2,18,96,96]
    const float* msk  = (const float*)d_in[2];  // mask   [2,9,96,96]
    const float* wt   = (const float*)d_in[3];  // weight [256,256,3,3]
    const float* bias = (const float*)d_in[4];  // bias   [256]
    float* out = (float*)d_out;                 // [2,256,96,96]

    {
        const int total = Bz * Cc * KK * Ss;     // 42,467,328
        const int threads = 256;
        const int blocks = (total + threads - 1) / threads;
        im2col_k<<<blocks, threads>>>(inp, off, msk);
    }
    {
        dim3 grid(Ss / BN, Oo / BM, Bz);          // (72, 2, 2)
        sgemm_k<<<grid, 256>>>(wt, bias, out);
    }
}

// round 3
// speedup vs baseline: 2.5061x; 2.5061x over previous
#include <cuda_runtime.h>
#include <cuda_bf16.h>
#include <cstdint>

// ---------------------------------------------------------------------------
// Problem constants
// ---------------------------------------------------------------------------
#define Bz   2
#define Cc   256
#define Oo   256
#define Ss   9216          // 96*96
#define CKk  2304          // 256*9
#define NCHUNK 36          // 2304 / 64 (K per chunk = 64)
#define NTILE  144         // 9216 / 64 (pixels per tile = 64)

// Packed weights:  [chunk][ Ah 32KB | Al 32KB ]  (256 rows x 64 bf16, SW128)
__device__ __align__(1024) unsigned char g_wA[(size_t)NCHUNK * 65536];
// Packed col: [b][n_t 144][chunk 36][ Bh 8KB | Bl 8KB ] (64 px x 64 bf16, SW128)
__device__ __align__(1024) unsigned char g_colB[(size_t)Bz * NTILE * NCHUNK * 16384];

#define SWZ(o) ((o) ^ (((o) >> 3) & 0x70))

__device__ __forceinline__ uint32_t smem_u32(const void* p) {
    uint32_t a;
    asm("{ .reg .u64 t; cvta.to.shared.u64 t, %1; cvt.u32.u64 %0, t; }"
        : "=r"(a) : "l"(p));
    return a;
}

// ---- portable async-copy + tensor-core helpers (NO sm_103a-only features) --
__device__ __forceinline__ void cp16(uint32_t dst, const void* src) {
    asm volatile("cp.async.cg.shared.global [%0], [%1], 16;"
                 :: "r"(dst), "l"(src) : "memory");
}
__device__ __forceinline__ void cp_commit() {
    asm volatile("cp.async.commit_group;" ::: "memory");
}
template <int N>
__device__ __forceinline__ void cp_wait() {
    asm volatile("cp.async.wait_group %0;" :: "n"(N) : "memory");
}
__device__ __forceinline__ void ldm4(uint32_t* r, uint32_t addr) {
    asm volatile("ldmatrix.sync.aligned.m8n8.x4.shared.b16 {%0,%1,%2,%3}, [%4];"
                 : "=r"(r[0]), "=r"(r[1]), "=r"(r[2]), "=r"(r[3]) : "r"(addr));
}
__device__ __forceinline__ void mma16816(float* d, const uint32_t* a,
                                         uint32_t b0, uint32_t b1) {
    asm volatile(
        "mma.sync.aligned.m16n8k16.row.col.f32.bf16.bf16.f32 "
        "{%0,%1,%2,%3}, {%4,%5,%6,%7}, {%8,%9}, {%0,%1,%2,%3};"
        : "+f"(d[0]), "+f"(d[1]), "+f"(d[2]), "+f"(d[3])
        : "r"(a[0]), "r"(a[1]), "r"(a[2]), "r"(a[3]), "r"(b0), "r"(b1));
}

// ---------------------------------------------------------------------------
// Kernel 1: pack weights -> bf16 hi/lo, SW128 swizzled chunk tiles
// ---------------------------------------------------------------------------
__global__ __launch_bounds__(256) void wpack_k(const float* __restrict__ w) {
    int t = blockIdx.x * 256 + threadIdx.x;   // 0 .. 294911
    int lane  = t & 31;
    int row   = (t >> 5) & 255;
    int chunk = t >> 13;
    int ck = chunk * 64 + 2 * lane;

    float2 wv = *(const float2*)(w + (size_t)row * CKk + ck);

    __nv_bfloat16 h0 = __float2bfloat16_rn(wv.x);
    __nv_bfloat16 h1 = __float2bfloat16_rn(wv.y);
    __nv_bfloat16 l0 = __float2bfloat16_rn(wv.x - __bfloat162float(h0));
    __nv_bfloat16 l1 = __float2bfloat16_rn(wv.y - __bfloat162float(h1));

    unsigned char* base = g_wA + (size_t)chunk * 65536;
    int off = SWZ(row * 128 + lane * 4);
    __nv_bfloat162 hp; hp.x = h0; hp.y = h1;
    __nv_bfloat162 lp; lp.x = l0; lp.y = l1;
    *(__nv_bfloat162*)(base + off)         = hp;
    *(__nv_bfloat162*)(base + 32768 + off) = lp;
}

// ---------------------------------------------------------------------------
// Kernel 2: modulated deformable im2col -> packed swizzled bf16 hi/lo tiles
// block = (chunk, n_t, b), 64 threads = 64 pixels.
// ---------------------------------------------------------------------------
__global__ __launch_bounds__(64) void im2col_k(
    const float* __restrict__ inp,   // [B,256,96,96]
    const float* __restrict__ off,   // [B,18,96,96]
    const float* __restrict__ msk)   // [B,9,96,96]
{
    __shared__ unsigned char sm[16384];

    const int p     = threadIdx.x;    // pixel within tile (0..63)
    const int chunk = blockIdx.x;     // 0..35
    const int n_t   = blockIdx.y;     // 0..143
    const int b     = blockIdx.z;

    const int s  = n_t * 64 + p;
    const int oh = s / 96;
    const int ow = s - oh * 96;

    float w00[9], w01[9], w10[9], w11[9];
    int   i00[9], i01[9], i10[9], i11[9];

#pragma unroll
    for (int k = 0; k < 9; k++) {
        float dy = off[((size_t)(b * 18 + 2 * k)) * Ss + s];
        float dx = off[((size_t)(b * 18 + 2 * k + 1)) * Ss + s];
        float m  = msk[((size_t)(b * 9 + k)) * Ss + s];
        float y = (float)(oh - 1 + k / 3) + dy;
        float x = (float)(ow - 1 + k % 3) + dx;
        float yf = floorf(y), xf = floorf(x);
        float wy = y - yf,    wx = x - xf;
        int iy = (int)yf, ix = (int)xf;
        float vy0 = (iy >= 0     && iy < 96)     ? 1.0f : 0.0f;
        float vy1 = (iy + 1 >= 0 && iy + 1 < 96) ? 1.0f : 0.0f;
        float vx0 = (ix >= 0     && ix < 96)     ? 1.0f : 0.0f;
        float vx1 = (ix + 1 >= 0 && ix + 1 < 96) ? 1.0f : 0.0f;
        int cy0 = min(max(iy, 0), 95),     cy1 = min(max(iy + 1, 0), 95);
        int cx0 = min(max(ix, 0), 95),     cx1 = min(max(ix + 1, 0), 95);
        i00[k] = cy0 * 96 + cx0;  i01[k] = cy0 * 96 + cx1;
        i10[k] = cy1 * 96 + cx0;  i11[k] = cy1 * 96 + cx1;
        w00[k] = m * (1.0f - wy) * (1.0f - wx) * vy0 * vx0;
        w01[k] = m * (1.0f - wy) * wx          * vy0 * vx1;
        w10[k] = m * wy * (1.0f - wx)          * vy1 * vx0;
        w11[k] = m * wy * wx                   * vy1 * vx1;
    }

    const int ckbase = chunk * 64;
    const int pbase  = p * 128;

#pragma unroll
    for (int k = 0; k < 9; k++) {
        int r = (k - ckbase) % 9;
        if (r < 0) r += 9;
        int c = (ckbase + r) / 9;
        const float* base = inp + ((size_t)(b * Cc + c)) * Ss;
        for (; r < 64; r += 9, base += Ss) {
            float val = w00[k] * __ldg(base + i00[k])
                      + w01[k] * __ldg(base + i01[k])
                      + w10[k] * __ldg(base + i10[k])
                      + w11[k] * __ldg(base + i11[k]);
            __nv_bfloat16 h = __float2bfloat16_rn(val);
            __nv_bfloat16 l = __float2bfloat16_rn(val - __bfloat162float(h));
            int sw = SWZ(pbase + r * 2);
            *(__nv_bfloat16*)(sm + sw)        = h;
            *(__nv_bfloat16*)(sm + 8192 + sw) = l;
        }
    }
    __syncthreads();

    // flush 16KB tile (coalesced)
    float4* g = (float4*)(g_colB + ((size_t)((b * NTILE + n_t) * NCHUNK + chunk)) * 16384);
    const float4* ss = (const float4*)sm;
#pragma unroll
    for (int i = p; i < 1024; i += 64) g[i] = ss[i];
}

// ---------------------------------------------------------------------------
// Kernel 3: bf16-split GEMM via mma.sync (m16n8k16), cp.async double buffer
// CTA tile: M=256, N=64. grid = (144 n-tiles, 2 batches). 256 threads.
// D += Ah*Bh + Ah*Bl + Al*Bh  (fp32 accumulators)
// ---------------------------------------------------------------------------
#define STAGE_BYTES 81920       // Ah 32K | Al 32K | Bh 8K | Bl 8K
#define SMEM_TOTAL  (2 * STAGE_BYTES)
#define OFF_AL 32768
#define OFF_BH 65536
#define OFF_BL 73728

__global__ __launch_bounds__(256) void gemm_mma(
    const float* __restrict__ bias, float* __restrict__ out)
{
    extern __shared__ __align__(128) unsigned char smem[];
    const uint32_t sb = smem_u32(smem);

    const int tid  = threadIdx.x;
    const int wid  = tid >> 5;
    const int lane = tid & 31;
    const int n_t  = blockIdx.x;
    const int b    = blockIdx.y;

    const unsigned char* gA = g_wA;
    const unsigned char* gB = g_colB + ((size_t)((b * NTILE + n_t) * NCHUNK)) * 16384;

    // prologue: load chunks 0 and 1
#pragma unroll
    for (int pre = 0; pre < 2; pre++) {
        uint32_t st = sb + pre * STAGE_BYTES;
        const unsigned char* a = gA + (size_t)pre * 65536;
        const unsigned char* bb = gB + (size_t)pre * 16384;
#pragma unroll
        for (int i = 0; i < 16; i++)
            cp16(st + (tid + i * 256) * 16, a + (tid + i * 256) * 16);
#pragma unroll
        for (int i = 0; i < 4; i++)
            cp16(st + OFF_BH + (tid + i * 256) * 16, bb + (tid + i * 256) * 16);
        cp_commit();
    }

    // per-warp tile: m base (64) and n base (32)
    const int wm = (wid & 3) * 64;
    const int wn = (wid >> 2) * 32;

    // ldmatrix lane address patterns (within SW128 rows of 128B)
    const int a_r   = (lane & 7) + ((lane >> 3) & 1) * 8;  // row within m16
    const int a_cb  = (lane >> 4) * 16;                    // k-half byte
    const int b_r   = (lane & 7) + (lane >> 4) * 8;        // n within n16
    const int b_cb  = ((lane >> 3) & 1) * 16;              // k-half byte

    float acc[4][4][4];
#pragma unroll
    for (int i = 0; i < 4; i++)
#pragma unroll
        for (int j = 0; j < 4; j++)
#pragma unroll
            for (int q = 0; q < 4; q++) acc[i][j][q] = 0.0f;

    for (int ch = 0; ch < NCHUNK; ch++) {
        const uint32_t st = sb + (ch & 1) * STAGE_BYTES;
        cp_wait<1>();
        __syncthreads();

#pragma unroll
        for (int ks = 0; ks < 4; ks++) {
            const int kb = ks * 32;   // byte offset of this k16 within the 128B row

            uint32_t Ah[4][4], Al[4][4];
#pragma unroll
            for (int mf = 0; mf < 4; mf++) {
                int row = wm + mf * 16 + a_r;
                uint32_t rel = row * 128 + ((kb + a_cb) ^ ((row & 7) * 16));
                ldm4(Ah[mf], st + rel);
                ldm4(Al[mf], st + OFF_AL + rel);
            }
            uint32_t Bh[2][4], Bl[2][4];
#pragma unroll
            for (int np = 0; np < 2; np++) {
                int row = wn + np * 16 + b_r;
                uint32_t rel = row * 128 + ((kb + b_cb) ^ ((row & 7) * 16));
                ldm4(Bh[np], st + OFF_BH + rel);
                ldm4(Bl[np], st + OFF_BL + rel);
            }

#pragma unroll
            for (int mf = 0; mf < 4; mf++)
#pragma unroll
                for (int nf = 0; nf < 4; nf++) {
                    uint32_t bh0 = Bh[nf >> 1][(nf & 1) * 2];
                    uint32_t bh1 = Bh[nf >> 1][(nf & 1) * 2 + 1];
                    uint32_t bl0 = Bl[nf >> 1][(nf & 1) * 2];
                    uint32_t bl1 = Bl[nf >> 1][(nf & 1) * 2 + 1];
                    mma16816(acc[mf][nf], Ah[mf], bh0, bh1);
                    mma16816(acc[mf][nf], Ah[mf], bl0, bl1);
                    mma16816(acc[mf][nf], Al[mf], bh0, bh1);
                }
        }

        __syncthreads();
        if (ch + 2 < NCHUNK) {
            const unsigned char* a = gA + (size_t)(ch + 2) * 65536;
            const unsigned char* bb = gB + (size_t)(ch + 2) * 16384;
#pragma unroll
            for (int i = 0; i < 16; i++)
                cp16(st + (tid + i * 256) * 16, a + (tid + i * 256) * 16);
#pragma unroll
            for (int i = 0; i < 4; i++)
                cp16(st + OFF_BH + (tid + i * 256) * 16, bb + (tid + i * 256) * 16);
        }
        cp_commit();   // keep group accounting uniform (empty groups are fine)
    }

    // ---- epilogue ----
    const int mrow = lane >> 2;          // 0..7
    const int ncol = (lane & 3) * 2;     // 0,2,4,6
#pragma unroll
    for (int mf = 0; mf < 4; mf++) {
        int m0 = wm + mf * 16 + mrow;
        float bv0 = __ldg(bias + m0);
        float bv8 = __ldg(bias + m0 + 8);
        float* r0 = out + ((size_t)(b * Oo + m0)) * Ss + n_t * 64;
        float* r8 = r0 + (size_t)8 * Ss;
#pragma unroll
        for (int nf = 0; nf < 4; nf++) {
            int n = wn + nf * 8 + ncol;
            float2 v0, v8;
            v0.x = acc[mf][nf][0] + bv0;  v0.y = acc[mf][nf][1] + bv0;
            v8.x = acc[mf][nf][2] + bv8;  v8.y = acc[mf][nf][3] + bv8;
            *(float2*)(r0 + n) = v0;
            *(float2*)(r8 + n) = v8;
        }
    }
}

// ---------------------------------------------------------------------------
extern "C" void kernel_launch(void* const* d_in, const int* in_sizes, int n_in,
                              void* d_out, int out_size)
{
    const float* inp  = (const float*)d_in[0];
    const float* off  = (const float*)d_in[1];
    const float* msk  = (const float*)d_in[2];
    const float* wt   = (const float*)d_in[3];
    const float* bias = (const float*)d_in[4];
    float* out = (float*)d_out;

    cudaFuncSetAttribute(gemm_mma, cudaFuncAttributeMaxDynamicSharedMemorySize,
                         SMEM_TOTAL);

    wpack_k<<<(NCHUNK * 8192) / 256, 256>>>(wt);
    {
        dim3 g(NCHUNK, NTILE, Bz);
        im2col_k<<<g, 64>>>(inp, off, msk);
    }
    {
        dim3 g(NTILE, Bz);
        gemm_mma<<<g, 256, SMEM_TOTAL>>>(bias, out);
    }
}

// round 4
// speedup vs baseline: 2.8675x; 1.1442x over previous
#include <cuda_runtime.h>
#include <cuda_bf16.h>
#include <cstdint>

// ---------------------------------------------------------------------------
// Problem constants
// ---------------------------------------------------------------------------
#define Bz   2
#define Cc   256
#define Oo   256
#define Ss   9216          // 96*96
#define CKk  2304          // 256*9
#define NCHUNK 36          // 2304 / 64 (K per chunk = 64); ck' = k*256 + c
#define NTILE  72          // 9216 / 128 (pixels per GEMM tile = 128)

// Transposed input: [B][HW][C] fp32
__device__ float g_inpT[(size_t)Bz * Ss * Cc];
// Packed weights:  [chunk][ Ah 32KB | Al 32KB ]  (256 rows x 64 bf16, SW128)
__device__ __align__(1024) unsigned char g_wA[(size_t)NCHUNK * 65536];
// Packed col: [b][n_t 72][chunk 36][ Bh 16KB | Bl 16KB ] (128 px x 64 bf16, SW128)
__device__ __align__(1024) unsigned char g_colB[(size_t)Bz * NTILE * NCHUNK * 32768];

#define SWZ(o) ((o) ^ (((o) >> 3) & 0x70))

__device__ __forceinline__ uint32_t smem_u32(const void* p) {
    uint32_t a;
    asm("{ .reg .u64 t; cvta.to.shared.u64 t, %1; cvt.u32.u64 %0, t; }"
        : "=r"(a) : "l"(p));
    return a;
}

// ---- portable async-copy + tensor-core helpers (NO sm_103a-only features) --
__device__ __forceinline__ void cp16(uint32_t dst, const void* src) {
    asm volatile("cp.async.cg.shared.global [%0], [%1], 16;"
                 :: "r"(dst), "l"(src) : "memory");
}
__device__ __forceinline__ void cp_commit() {
    asm volatile("cp.async.commit_group;" ::: "memory");
}
template <int N>
__device__ __forceinline__ void cp_wait() {
    asm volatile("cp.async.wait_group %0;" :: "n"(N) : "memory");
}
__device__ __forceinline__ void ldm4(uint32_t* r, uint32_t addr) {
    asm volatile("ldmatrix.sync.aligned.m8n8.x4.shared.b16 {%0,%1,%2,%3}, [%4];"
                 : "=r"(r[0]), "=r"(r[1]), "=r"(r[2]), "=r"(r[3]) : "r"(addr));
}
__device__ __forceinline__ void mma16816(float* d, const uint32_t* a,
                                         uint32_t b0, uint32_t b1) {
    asm volatile(
        "mma.sync.aligned.m16n8k16.row.col.f32.bf16.bf16.f32 "
        "{%0,%1,%2,%3}, {%4,%5,%6,%7}, {%8,%9}, {%0,%1,%2,%3};"
        : "+f"(d[0]), "+f"(d[1]), "+f"(d[2]), "+f"(d[3])
        : "r"(a[0]), "r"(a[1]), "r"(a[2]), "r"(a[3]), "r"(b0), "r"(b1));
}

// ---------------------------------------------------------------------------
// Kernel 0: transpose input [B][C][HW] -> [B][HW][C]
// ---------------------------------------------------------------------------
__global__ __launch_bounds__(256) void transpose_k(const float* __restrict__ inp) {
    __shared__ float t[32][33];
    const int tx = threadIdx.x & 31;
    const int ty = threadIdx.x >> 5;       // 0..7
    const int s0 = blockIdx.x * 32;        // 288 tiles
    const int c0 = blockIdx.y * 32;        // 8 tiles
    const int b  = blockIdx.z;

#pragma unroll
    for (int j = 0; j < 4; j++) {
        int c = c0 + ty + j * 8;
        t[tx][ty + j * 8] = inp[((size_t)(b * Cc + c)) * Ss + s0 + tx];
    }
    __syncthreads();
#pragma unroll
    for (int j = 0; j < 4; j++) {
        int s = s0 + ty + j * 8;
        g_inpT[((size_t)b * Ss + s) * Cc + c0 + tx] = t[ty + j * 8][tx];
    }
}

// ---------------------------------------------------------------------------
// Kernel 1: pack weights -> bf16 hi/lo, SW128 tiles, ck' = k*256 + c order
// ---------------------------------------------------------------------------
__global__ __launch_bounds__(256) void wpack_k(const float* __restrict__ w) {
    int t = blockIdx.x * 256 + threadIdx.x;   // 0 .. 294911
    int lane  = t & 31;
    int row   = (t >> 5) & 255;
    int chunk = t >> 13;
    int k  = chunk >> 2;
    int c  = (chunk & 3) * 64 + 2 * lane;

    float wa = w[(size_t)row * CKk + c * 9 + k];
    float wb = w[(size_t)row * CKk + (c + 1) * 9 + k];

    __nv_bfloat16 h0 = __float2bfloat16_rn(wa);
    __nv_bfloat16 h1 = __float2bfloat16_rn(wb);
    __nv_bfloat16 l0 = __float2bfloat16_rn(wa - __bfloat162float(h0));
    __nv_bfloat16 l1 = __float2bfloat16_rn(wb - __bfloat162float(h1));

    unsigned char* base = g_wA + (size_t)chunk * 65536;
    int off = SWZ(row * 128 + lane * 4);
    __nv_bfloat162 hp; hp.x = h0; hp.y = h1;
    __nv_bfloat162 lp; lp.x = l0; lp.y = l1;
    *(__nv_bfloat162*)(base + off)         = hp;
    *(__nv_bfloat162*)(base + 32768 + off) = lp;
}

// ---------------------------------------------------------------------------
// Kernel 2: modulated deformable im2col, coalesced via transposed input.
// One warp = one (pixel, chunk): chunk = (k, 64-channel group).
// Lanes cover channels (float2 each) -> every bilinear tap is a 256B
// coalesced load. Output row (128B, swizzled-in-row) written directly to
// global in a single wavefront.
// ---------------------------------------------------------------------------
__global__ __launch_bounds__(256) void im2col_k(
    const float* __restrict__ off,   // [B,18,96,96]
    const float* __restrict__ msk)   // [B,9,96,96]
{
    const int lane  = threadIdx.x & 31;
    const int warp  = threadIdx.x >> 5;
    const int chunk = blockIdx.x;            // 0..35
    const int b     = blockIdx.z;
    const int s     = blockIdx.y * 8 + warp; // 0..9215

    const int k  = chunk >> 2;
    const int c0 = (chunk & 3) * 64;

    const int oh = s / 96;
    const int ow = s - oh * 96;

    float dy = off[((size_t)(b * 18 + 2 * k)) * Ss + s];
    float dx = off[((size_t)(b * 18 + 2 * k + 1)) * Ss + s];
    float m  = msk[((size_t)(b * 9 + k)) * Ss + s];

    float y = (float)(oh - 1 + k / 3) + dy;
    float x = (float)(ow - 1 + k % 3) + dx;
    float yf = floorf(y), xf = floorf(x);
    float wy = y - yf,    wx = x - xf;
    int iy = (int)yf, ix = (int)xf;

    float vy0 = (iy >= 0     && iy < 96)     ? 1.0f : 0.0f;
    float vy1 = (iy + 1 >= 0 && iy + 1 < 96) ? 1.0f : 0.0f;
    float vx0 = (ix >= 0     && ix < 96)     ? 1.0f : 0.0f;
    float vx1 = (ix + 1 >= 0 && ix + 1 < 96) ? 1.0f : 0.0f;
    int cy0 = min(max(iy, 0), 95),     cy1 = min(max(iy + 1, 0), 95);
    int cx0 = min(max(ix, 0), 95),     cx1 = min(max(ix + 1, 0), 95);

    size_t i00 = (size_t)(cy0 * 96 + cx0) * Cc;
    size_t i01 = (size_t)(cy0 * 96 + cx1) * Cc;
    size_t i10 = (size_t)(cy1 * 96 + cx0) * Cc;
    size_t i11 = (size_t)(cy1 * 96 + cx1) * Cc;

    float w00 = m * (1.0f - wy) * (1.0f - wx) * vy0 * vx0;
    float w01 = m * (1.0f - wy) * wx          * vy0 * vx1;
    float w10 = m * wy * (1.0f - wx)          * vy1 * vx0;
    float w11 = m * wy * wx                   * vy1 * vx1;

    const float* bp = g_inpT + (size_t)b * Ss * Cc + c0 + lane * 2;
    float2 v00 = *(const float2*)(bp + i00);
    float2 v01 = *(const float2*)(bp + i01);
    float2 v10 = *(const float2*)(bp + i10);
    float2 v11 = *(const float2*)(bp + i11);

    float val0 = w00 * v00.x + w01 * v01.x + w10 * v10.x + w11 * v11.x;
    float val1 = w00 * v00.y + w01 * v01.y + w10 * v10.y + w11 * v11.y;

    __nv_bfloat16 h0 = __float2bfloat16_rn(val0);
    __nv_bfloat16 h1 = __float2bfloat16_rn(val1);
    __nv_bfloat16 l0 = __float2bfloat16_rn(val0 - __bfloat162float(h0));
    __nv_bfloat16 l1 = __float2bfloat16_rn(val1 - __bfloat162float(h1));

    unsigned char* dst = g_colB
        + ((size_t)((b * NTILE + (s >> 7)) * NCHUNK + chunk)) * 32768;
    const int px = s & 127;
    const int sw = SWZ(px * 128 + lane * 4);
    __nv_bfloat162 hp; hp.x = h0; hp.y = h1;
    __nv_bfloat162 lp; lp.x = l0; lp.y = l1;
    *(__nv_bfloat162*)(dst + sw)         = hp;
    *(__nv_bfloat162*)(dst + 16384 + sw) = lp;
}

// ---------------------------------------------------------------------------
// Kernel 3: bf16-split GEMM via mma.sync (m16n8k16), cp.async double buffer
// CTA tile: M=256, N=128. grid = (72 n-tiles, 2 batches). 512 threads.
// D += Ah*Bh + Ah*Bl + Al*Bh  (fp32 accumulators)
// ---------------------------------------------------------------------------
#define STAGE_BYTES 98304       // Ah 32K | Al 32K | Bh 16K | Bl 16K
#define SMEM_TOTAL  (2 * STAGE_BYTES)
#define OFF_AL 32768
#define OFF_BH 65536
#define OFF_BL 81920

__global__ __launch_bounds__(512) void gemm_mma(
    const float* __restrict__ bias, float* __restrict__ out)
{
    extern __shared__ __align__(128) unsigned char smem[];
    const uint32_t sb = smem_u32(smem);

    const int tid  = threadIdx.x;
    const int wid  = tid >> 5;
    const int lane = tid & 31;
    const int n_t  = blockIdx.x;
    const int b    = blockIdx.y;

    const unsigned char* gA = g_wA;
    const unsigned char* gB = g_colB + ((size_t)((b * NTILE + n_t) * NCHUNK)) * 32768;

    // prologue: load chunks 0 and 1
#pragma unroll
    for (int pre = 0; pre < 2; pre++) {
        uint32_t st = sb + pre * STAGE_BYTES;
        const unsigned char* a  = gA + (size_t)pre * 65536;
        const unsigned char* bb = gB + (size_t)pre * 32768;
#pragma unroll
        for (int i = 0; i < 8; i++)
            cp16(st + (tid + i * 512) * 16, a + (tid + i * 512) * 16);
#pragma unroll
        for (int i = 0; i < 4; i++)
            cp16(st + OFF_BH + (tid + i * 512) * 16, bb + (tid + i * 512) * 16);
        cp_commit();
    }

    // per-warp tile: 16 warps = 4(m) x 4(n); warp tile 64(m) x 32(n)
    const int wm = (wid & 3) * 64;
    const int wn = (wid >> 2) * 32;

    const int a_r  = (lane & 7) + ((lane >> 3) & 1) * 8;
    const int a_cb = (lane >> 4) * 16;
    const int b_r  = (lane & 7) + (lane >> 4) * 8;
    const int b_cb = ((lane >> 3) & 1) * 16;

    float acc[4][4][4];
#pragma unroll
    for (int i = 0; i < 4; i++)
#pragma unroll
        for (int j = 0; j < 4; j++)
#pragma unroll
            for (int q = 0; q < 4; q++) acc[i][j][q] = 0.0f;

    for (int ch = 0; ch < NCHUNK; ch++) {
        const uint32_t st = sb + (ch & 1) * STAGE_BYTES;
        cp_wait<1>();
        __syncthreads();

#pragma unroll
        for (int ks = 0; ks < 4; ks++) {
            const int kb = ks * 32;

            uint32_t Ah[4][4], Al[4][4];
#pragma unroll
            for (int mf = 0; mf < 4; mf++) {
                int row = wm + mf * 16 + a_r;
                uint32_t rel = row * 128 + ((kb + a_cb) ^ ((row & 7) * 16));
                ldm4(Ah[mf], st + rel);
                ldm4(Al[mf], st + OFF_AL + rel);
            }
            uint32_t Bh[2][4], Bl[2][4];
#pragma unroll
            for (int np = 0; np < 2; np++) {
                int row = wn + np * 16 + b_r;
                uint32_t rel = row * 128 + ((kb + b_cb) ^ ((row & 7) * 16));
                ldm4(Bh[np], st + OFF_BH + rel);
                ldm4(Bl[np], st + OFF_BL + rel);
            }

#pragma unroll
            for (int mf = 0; mf < 4; mf++)
#pragma unroll
                for (int nf = 0; nf < 4; nf++) {
                    uint32_t bh0 = Bh[nf >> 1][(nf & 1) * 2];
                    uint32_t bh1 = Bh[nf >> 1][(nf & 1) * 2 + 1];
                    uint32_t bl0 = Bl[nf >> 1][(nf & 1) * 2];
                    uint32_t bl1 = Bl[nf >> 1][(nf & 1) * 2 + 1];
                    mma16816(acc[mf][nf], Ah[mf], bh0, bh1);
                    mma16816(acc[mf][nf], Ah[mf], bl0, bl1);
                    mma16816(acc[mf][nf], Al[mf], bh0, bh1);
                }
        }

        __syncthreads();
        if (ch + 2 < NCHUNK) {
            const unsigned char* a  = gA + (size_t)(ch + 2) * 65536;
            const unsigned char* bb = gB + (size_t)(ch + 2) * 32768;
#pragma unroll
            for (int i = 0; i < 8; i++)
                cp16(st + (tid + i * 512) * 16, a + (tid + i * 512) * 16);
#pragma unroll
            for (int i = 0; i < 4; i++)
                cp16(st + OFF_BH + (tid + i * 512) * 16, bb + (tid + i * 512) * 16);
        }
        cp_commit();   // uniform group accounting (empty groups fine)
    }

    // ---- epilogue ----
    const int mrow = lane >> 2;
    const int ncol = (lane & 3) * 2;
#pragma unroll
    for (int mf = 0; mf < 4; mf++) {
        int m0 = wm + mf * 16 + mrow;
        float bv0 = __ldg(bias + m0);
        float bv8 = __ldg(bias + m0 + 8);
        float* r0 = out + ((size_t)(b * Oo + m0)) * Ss + n_t * 128;
        float* r8 = r0 + (size_t)8 * Ss;
#pragma unroll
        for (int nf = 0; nf < 4; nf++) {
            int n = wn + nf * 8 + ncol;
            float2 v0, v8;
            v0.x = acc[mf][nf][0] + bv0;  v0.y = acc[mf][nf][1] + bv0;
            v8.x = acc[mf][nf][2] + bv8;  v8.y = acc[mf][nf][3] + bv8;
            *(float2*)(r0 + n) = v0;
            *(float2*)(r8 + n) = v8;
        }
    }
}

// ---------------------------------------------------------------------------
extern "C" void kernel_launch(void* const* d_in, const int* in_sizes, int n_in,
                              void* d_out, int out_size)
{
    const float* inp  = (const float*)d_in[0];
    const float* off  = (const float*)d_in[1];
    const float* msk  = (const float*)d_in[2];
    const float* wt   = (const float*)d_in[3];
    const float* bias = (const float*)d_in[4];
    float* out = (float*)d_out;

    cudaFuncSetAttribute(gemm_mma, cudaFuncAttributeMaxDynamicSharedMemorySize,
                         SMEM_TOTAL);

    {
        dim3 g(Ss / 32, Cc / 32, Bz);      // (288, 8, 2)
        transpose_k<<<g, 256>>>(inp);
    }
    wpack_k<<<(NCHUNK * 8192) / 256, 256>>>(wt);
    {
        dim3 g(NCHUNK, Ss / 8, Bz);        // (36, 1152, 2)
        im2col_k<<<g, 256>>>(off, msk);
    }
    {
        dim3 g(NTILE, Bz);                 // (72, 2)
        gemm_mma<<<g, 512, SMEM_TOTAL>>>(bias, out);
    }
}

// round 5
// speedup vs baseline: 3.8462x; 1.3413x over previous
#include <cuda_runtime.h>
#include <cuda_bf16.h>
#include <cstdint>

// ---------------------------------------------------------------------------
// Problem constants
// ---------------------------------------------------------------------------
#define Bz   2
#define Cc   256
#define Oo   256
#define Ss   9216          // 96*96
#define CKk  2304          // 256*9
#define NCHUNK 36          // 2304 / 64 (K per chunk = 64); ck' = k*256 + c
#define NTILE  72          // 9216 / 128 (pixels per GEMM tile = 128)

// Transposed input: [B][HW][C] fp32
__device__ float g_inpT[(size_t)Bz * Ss * Cc];
// Packed weights:  [chunk][ Ah 32KB | Al 32KB ]  (256 rows x 64 bf16, SW128)
__device__ __align__(1024) unsigned char g_wA[(size_t)NCHUNK * 65536];

#define SWZ(o) ((o) ^ (((o) >> 3) & 0x70))

__device__ __forceinline__ uint32_t smem_u32(const void* p) {
    uint32_t a;
    asm("{ .reg .u64 t; cvta.to.shared.u64 t, %1; cvt.u32.u64 %0, t; }"
        : "=r"(a) : "l"(p));
    return a;
}

// ---- portable async-copy + tensor-core helpers (NO sm_103a-only features) --
__device__ __forceinline__ void cp16(uint32_t dst, const void* src) {
    asm volatile("cp.async.cg.shared.global [%0], [%1], 16;"
                 :: "r"(dst), "l"(src) : "memory");
}
__device__ __forceinline__ void cp_commit() {
    asm volatile("cp.async.commit_group;" ::: "memory");
}
template <int N>
__device__ __forceinline__ void cp_wait() {
    asm volatile("cp.async.wait_group %0;" :: "n"(N) : "memory");
}
__device__ __forceinline__ void ldm4(uint32_t* r, uint32_t addr) {
    asm volatile("ldmatrix.sync.aligned.m8n8.x4.shared.b16 {%0,%1,%2,%3}, [%4];"
                 : "=r"(r[0]), "=r"(r[1]), "=r"(r[2]), "=r"(r[3]) : "r"(addr));
}
__device__ __forceinline__ void mma16816(float* d, const uint32_t* a,
                                         uint32_t b0, uint32_t b1) {
    asm volatile(
        "mma.sync.aligned.m16n8k16.row.col.f32.bf16.bf16.f32 "
        "{%0,%1,%2,%3}, {%4,%5,%6,%7}, {%8,%9}, {%0,%1,%2,%3};"
        : "+f"(d[0]), "+f"(d[1]), "+f"(d[2]), "+f"(d[3])
        : "r"(a[0]), "r"(a[1]), "r"(a[2]), "r"(a[3]), "r"(b0), "r"(b1));
}

// ---------------------------------------------------------------------------
// Kernel 0: transpose input [B][C][HW] -> [B][HW][C]
// ---------------------------------------------------------------------------
__global__ __launch_bounds__(256) void transpose_k(const float* __restrict__ inp) {
    __shared__ float t[32][33];
    const int tx = threadIdx.x & 31;
    const int ty = threadIdx.x >> 5;
    const int s0 = blockIdx.x * 32;
    const int c0 = blockIdx.y * 32;
    const int b  = blockIdx.z;

#pragma unroll
    for (int j = 0; j < 4; j++) {
        int c = c0 + ty + j * 8;
        t[tx][ty + j * 8] = inp[((size_t)(b * Cc + c)) * Ss + s0 + tx];
    }
    __syncthreads();
#pragma unroll
    for (int j = 0; j < 4; j++) {
        int s = s0 + ty + j * 8;
        g_inpT[((size_t)b * Ss + s) * Cc + c0 + tx] = t[ty + j * 8][tx];
    }
}

// ---------------------------------------------------------------------------
// Kernel 1: pack weights -> bf16 hi/lo, SW128 tiles, ck' = k*256 + c order
// ---------------------------------------------------------------------------
__global__ __launch_bounds__(256) void wpack_k(const float* __restrict__ w) {
    int t = blockIdx.x * 256 + threadIdx.x;
    int lane  = t & 31;
    int row   = (t >> 5) & 255;
    int chunk = t >> 13;
    int k  = chunk >> 2;
    int c  = (chunk & 3) * 64 + 2 * lane;

    float wa = w[(size_t)row * CKk + c * 9 + k];
    float wb = w[(size_t)row * CKk + (c + 1) * 9 + k];

    __nv_bfloat16 h0 = __float2bfloat16_rn(wa);
    __nv_bfloat16 h1 = __float2bfloat16_rn(wb);
    __nv_bfloat16 l0 = __float2bfloat16_rn(wa - __bfloat162float(h0));
    __nv_bfloat16 l1 = __float2bfloat16_rn(wb - __bfloat162float(h1));

    unsigned char* base = g_wA + (size_t)chunk * 65536;
    int off = SWZ(row * 128 + lane * 4);
    __nv_bfloat162 hp; hp.x = h0; hp.y = h1;
    __nv_bfloat162 lp; lp.x = l0; lp.y = l1;
    *(__nv_bfloat162*)(base + off)         = hp;
    *(__nv_bfloat162*)(base + 32768 + off) = lp;
}

// ---------------------------------------------------------------------------
// Fused kernel: deformable-gather producer + bf16-split mma.sync GEMM
// CTA: M=256, N=128 (one n-tile of 128 pixels), 512 threads, grid (72, 2).
// Smem: A double buffer (2x64K) | B double buffer (2x32K) | coords (27.6K)
// ---------------------------------------------------------------------------
#define SM_A     0
#define A_STAGE  65536
#define SM_B     131072
#define B_STAGE  32768
#define SM_CRD   196608
#define SMEM_TOTAL 224256     // 196608 + 1152*24

struct __align__(8) Crd { uint32_t i01, i23; float w00, w01, w10, w11; };

struct PTask {
    float2 v00, v01, v10, v11;
    float w00, w01, w10, w11;
    int sw;
};

__device__ __forceinline__ PTask prod_issue(const Crd* crd, const float* bp,
                                            int px, int k, int lane) {
    PTask t;
    Crd c = crd[px * 9 + k];
    int i00 = c.i01 & 0xffff, i01 = c.i01 >> 16;
    int i10 = c.i23 & 0xffff, i11 = c.i23 >> 16;
    t.v00 = *(const float2*)(bp + (size_t)i00 * Cc);
    t.v01 = *(const float2*)(bp + (size_t)i01 * Cc);
    t.v10 = *(const float2*)(bp + (size_t)i10 * Cc);
    t.v11 = *(const float2*)(bp + (size_t)i11 * Cc);
    t.w00 = c.w00; t.w01 = c.w01; t.w10 = c.w10; t.w11 = c.w11;
    t.sw  = SWZ(px * 128 + lane * 4);
    return t;
}

__device__ __forceinline__ void prod_complete(const PTask& t, unsigned char* bh) {
    float val0 = t.w00 * t.v00.x + t.w01 * t.v01.x + t.w10 * t.v10.x + t.w11 * t.v11.x;
    float val1 = t.w00 * t.v00.y + t.w01 * t.v01.y + t.w10 * t.v10.y + t.w11 * t.v11.y;
    __nv_bfloat16 h0 = __float2bfloat16_rn(val0);
    __nv_bfloat16 h1 = __float2bfloat16_rn(val1);
    __nv_bfloat16 l0 = __float2bfloat16_rn(val0 - __bfloat162float(h0));
    __nv_bfloat16 l1 = __float2bfloat16_rn(val1 - __bfloat162float(h1));
    __nv_bfloat162 hp; hp.x = h0; hp.y = h1;
    __nv_bfloat162 lp; lp.x = l0; lp.y = l1;
    *(__nv_bfloat162*)(bh + t.sw)         = hp;
    *(__nv_bfloat162*)(bh + 16384 + t.sw) = lp;
}

__global__ __launch_bounds__(512) void gemm_fused(
    const float* __restrict__ off,    // [B,18,96,96]
    const float* __restrict__ msk,    // [B,9,96,96]
    const float* __restrict__ bias,
    float* __restrict__ out)
{
    extern __shared__ __align__(128) unsigned char smem[];
    const uint32_t sb = smem_u32(smem);

    const int tid  = threadIdx.x;
    const int wid  = tid >> 5;
    const int lane = tid & 31;
    const int n_t  = blockIdx.x;
    const int b    = blockIdx.y;

    Crd* crd = (Crd*)(smem + SM_CRD);
    const float* inpT_b = g_inpT + (size_t)b * Ss * Cc;

    // ---- coordinate/weight setup for this CTA's 128 pixels x 9 taps ----
    for (int r = tid; r < 128 * 9; r += 512) {
        int px = r / 9;
        int k  = r - px * 9;
        int s  = n_t * 128 + px;
        int oh = s / 96;
        int ow = s - oh * 96;

        float dy = off[((size_t)(b * 18 + 2 * k)) * Ss + s];
        float dx = off[((size_t)(b * 18 + 2 * k + 1)) * Ss + s];
        float m  = msk[((size_t)(b * 9 + k)) * Ss + s];

        float y = (float)(oh - 1 + k / 3) + dy;
        float x = (float)(ow - 1 + k % 3) + dx;
        float yf = floorf(y), xf = floorf(x);
        float wy = y - yf,    wx = x - xf;
        int iy = (int)yf, ix = (int)xf;

        float vy0 = (iy >= 0     && iy < 96)     ? 1.0f : 0.0f;
        float vy1 = (iy + 1 >= 0 && iy + 1 < 96) ? 1.0f : 0.0f;
        float vx0 = (ix >= 0     && ix < 96)     ? 1.0f : 0.0f;
        float vx1 = (ix + 1 >= 0 && ix + 1 < 96) ? 1.0f : 0.0f;
        int cy0 = min(max(iy, 0), 95),     cy1 = min(max(iy + 1, 0), 95);
        int cx0 = min(max(ix, 0), 95),     cx1 = min(max(ix + 1, 0), 95);

        Crd c;
        c.i01 = (uint32_t)(cy0 * 96 + cx0) | ((uint32_t)(cy0 * 96 + cx1) << 16);
        c.i23 = (uint32_t)(cy1 * 96 + cx0) | ((uint32_t)(cy1 * 96 + cx1) << 16);
        c.w00 = m * (1.0f - wy) * (1.0f - wx) * vy0 * vx0;
        c.w01 = m * (1.0f - wy) * wx          * vy0 * vx1;
        c.w10 = m * wy * (1.0f - wx)          * vy1 * vx0;
        c.w11 = m * wy * wx                   * vy1 * vx1;
        crd[r] = c;
    }
    __syncthreads();

    // ---- prologue: produce B chunk 0; prefetch A chunks 0,1 ----
    {
        unsigned char* bh0 = smem + SM_B;      // stage 0
        const float* bp = inpT_b + 0 * 64 + lane * 2;   // chunk 0: k=0, cg=0
#pragma unroll
        for (int e = 0; e < 8; e++) {
            PTask t = prod_issue(crd, bp, wid * 8 + e, 0, lane);
            prod_complete(t, bh0);
        }
    }
#pragma unroll
    for (int pre = 0; pre < 2; pre++) {
        uint32_t st = sb + SM_A + pre * A_STAGE;
        const unsigned char* a = g_wA + (size_t)pre * 65536;
#pragma unroll
        for (int i = 0; i < 8; i++)
            cp16(st + (tid + i * 512) * 16, a + (tid + i * 512) * 16);
        cp_commit();
    }

    // per-warp MMA tile: 16 warps = 4(m) x 4(n); warp tile 64(m) x 32(n)
    const int wm = (wid & 3) * 64;
    const int wn = (wid >> 2) * 32;

    const int a_r  = (lane & 7) + ((lane >> 3) & 1) * 8;
    const int a_cb = (lane >> 4) * 16;
    const int b_r  = (lane & 7) + (lane >> 4) * 8;
    const int b_cb = ((lane >> 3) & 1) * 16;

    float acc[4][4][4];
#pragma unroll
    for (int i = 0; i < 4; i++)
#pragma unroll
        for (int j = 0; j < 4; j++)
#pragma unroll
            for (int q = 0; q < 4; q++) acc[i][j][q] = 0.0f;

    for (int ch = 0; ch < NCHUNK; ch++) {
        const int cur = ch & 1;
        const uint32_t stA = sb + SM_A + cur * A_STAGE;
        const uint32_t stB = sb + SM_B + cur * B_STAGE;

        cp_wait<1>();
        __syncthreads();    // A(ch) arrived; B(ch) sealed; B(1-cur) free

        // producer setup for chunk ch+1 (written into the other B stage)
        const bool prod = (ch + 1 < NCHUNK);
        const int pk  = (ch + 1) >> 2;
        const int pcg = (ch + 1) & 3;
        unsigned char* bdst = smem + SM_B + (1 - cur) * B_STAGE;
        const float* bp = inpT_b + pcg * 64 + lane * 2;
        const int pxb = wid * 8;

        PTask tk0, tk1;
        if (prod) {
            tk0 = prod_issue(crd, bp, pxb + 0, pk, lane);
            tk1 = prod_issue(crd, bp, pxb + 1, pk, lane);
        }

#pragma unroll
        for (int ks = 0; ks < 4; ks++) {
            const int kb = ks * 32;

            uint32_t Bh[2][4], Bl[2][4];
#pragma unroll
            for (int np = 0; np < 2; np++) {
                int row = wn + np * 16 + b_r;
                uint32_t rel = row * 128 + ((kb + b_cb) ^ ((row & 7) * 16));
                ldm4(Bh[np], stB + rel);
                ldm4(Bl[np], stB + 16384 + rel);
            }

#pragma unroll
            for (int mf = 0; mf < 4; mf++) {
                int row = wm + mf * 16 + a_r;
                uint32_t rel = row * 128 + ((kb + a_cb) ^ ((row & 7) * 16));
                uint32_t Ah[4], Al[4];
                ldm4(Ah, stA + rel);
                ldm4(Al, stA + 32768 + rel);
#pragma unroll
                for (int nf = 0; nf < 4; nf++) {
                    uint32_t bh0 = Bh[nf >> 1][(nf & 1) * 2];
                    uint32_t bh1 = Bh[nf >> 1][(nf & 1) * 2 + 1];
                    uint32_t bl0 = Bl[nf >> 1][(nf & 1) * 2];
                    uint32_t bl1 = Bl[nf >> 1][(nf & 1) * 2 + 1];
                    mma16816(acc[mf][nf], Ah, bh0, bh1);
                    mma16816(acc[mf][nf], Ah, bl0, bl1);
                    mma16816(acc[mf][nf], Al, bh0, bh1);
                }
            }

            if (prod) {
                prod_complete(tk0, bdst);
                prod_complete(tk1, bdst);
                if (ks < 3) {
                    tk0 = prod_issue(crd, bp, pxb + 2 * (ks + 1),     pk, lane);
                    tk1 = prod_issue(crd, bp, pxb + 2 * (ks + 1) + 1, pk, lane);
                }
            }
        }

        __syncthreads();    // B(ch+1) fully written; A(ch) fully consumed
        if (ch + 2 < NCHUNK) {
            const unsigned char* a = g_wA + (size_t)(ch + 2) * 65536;
#pragma unroll
            for (int i = 0; i < 8; i++)
                cp16(stA + (tid + i * 512) * 16, a + (tid + i * 512) * 16);
        }
        cp_commit();   // uniform group accounting
    }

    // ---- epilogue ----
    const int mrow = lane >> 2;
    const int ncol = (lane & 3) * 2;
#pragma unroll
    for (int mf = 0; mf < 4; mf++) {
        int m0 = wm + mf * 16 + mrow;
        float bv0 = __ldg(bias + m0);
        float bv8 = __ldg(bias + m0 + 8);
        float* r0 = out + ((size_t)(b * Oo + m0)) * Ss + n_t * 128;
        float* r8 = r0 + (size_t)8 * Ss;
#pragma unroll
        for (int nf = 0; nf < 4; nf++) {
            int n = wn + nf * 8 + ncol;
            float2 v0, v8;
            v0.x = acc[mf][nf][0] + bv0;  v0.y = acc[mf][nf][1] + bv0;
            v8.x = acc[mf][nf][2] + bv8;  v8.y = acc[mf][nf][3] + bv8;
            *(float2*)(r0 + n) = v0;
            *(float2*)(r8 + n) = v8;
        }
    }
}

// ---------------------------------------------------------------------------
extern "C" void kernel_launch(void* const* d_in, const int* in_sizes, int n_in,
                              void* d_out, int out_size)
{
    const float* inp  = (const float*)d_in[0];
    const float* off  = (const float*)d_in[1];
    const float* msk  = (const float*)d_in[2];
    const float* wt   = (const float*)d_in[3];
    const float* bias = (const float*)d_in[4];
    float* out = (float*)d_out;

    cudaFuncSetAttribute(gemm_fused, cudaFuncAttributeMaxDynamicSharedMemorySize,
                         SMEM_TOTAL);

    {
        dim3 g(Ss / 32, Cc / 32, Bz);      // (288, 8, 2)
        transpose_k<<<g, 256>>>(inp);
    }
    wpack_k<<<(NCHUNK * 8192) / 256, 256>>>(wt);
    {
        dim3 g(NTILE, Bz);                 // (72, 2)
        gemm_fused<<<g, 512, SMEM_TOTAL>>>(off, msk, bias, out);
    }
}

// round 6
// speedup vs baseline: 5.4454x; 1.4158x over previous
#include <cuda_runtime.h>
#include <cuda_fp16.h>
#include <cstdint>

// ---------------------------------------------------------------------------
// Problem constants
// ---------------------------------------------------------------------------
#define Bz   2
#define Cc   256
#define Oo   256
#define Ss   9216          // 96*96
#define CKk  2304          // 256*9
#define NCHUNK 36          // 2304 / 64 (K per chunk = 64); ck' = k*256 + c
#define NTILE  72          // 9216 / 128 (pixels per GEMM tile = 128)

// Transposed input: [B][HW][C] fp32
__device__ float g_inpT[(size_t)Bz * Ss * Cc];
// Packed weights: [chunk][256 rows x 64 fp16, SW128] = 32KB per chunk
__device__ __align__(1024) unsigned char g_wA[(size_t)NCHUNK * 32768];

#define SWZ(o) ((o) ^ (((o) >> 3) & 0x70))

__device__ __forceinline__ uint32_t smem_u32(const void* p) {
    uint32_t a;
    asm("{ .reg .u64 t; cvta.to.shared.u64 t, %1; cvt.u32.u64 %0, t; }"
        : "=r"(a) : "l"(p));
    return a;
}

// ---- portable async-copy + tensor-core helpers (NO sm_103a-only features) --
__device__ __forceinline__ void cp16(uint32_t dst, const void* src) {
    asm volatile("cp.async.cg.shared.global [%0], [%1], 16;"
                 :: "r"(dst), "l"(src) : "memory");
}
__device__ __forceinline__ void cp_commit() {
    asm volatile("cp.async.commit_group;" ::: "memory");
}
template <int N>
__device__ __forceinline__ void cp_wait() {
    asm volatile("cp.async.wait_group %0;" :: "n"(N) : "memory");
}
__device__ __forceinline__ void ldm4(uint32_t* r, uint32_t addr) {
    asm volatile("ldmatrix.sync.aligned.m8n8.x4.shared.b16 {%0,%1,%2,%3}, [%4];"
                 : "=r"(r[0]), "=r"(r[1]), "=r"(r[2]), "=r"(r[3]) : "r"(addr));
}
__device__ __forceinline__ void mma16816(float* d, const uint32_t* a,
                                         uint32_t b0, uint32_t b1) {
    asm volatile(
        "mma.sync.aligned.m16n8k16.row.col.f32.f16.f16.f32 "
        "{%0,%1,%2,%3}, {%4,%5,%6,%7}, {%8,%9}, {%0,%1,%2,%3};"
        : "+f"(d[0]), "+f"(d[1]), "+f"(d[2]), "+f"(d[3])
        : "r"(a[0]), "r"(a[1]), "r"(a[2]), "r"(a[3]), "r"(b0), "r"(b1));
}

// ---------------------------------------------------------------------------
// Kernel 0: transpose input [B][C][HW] -> [B][HW][C]
// ---------------------------------------------------------------------------
__global__ __launch_bounds__(256) void transpose_k(const float* __restrict__ inp) {
    __shared__ float t[32][33];
    const int tx = threadIdx.x & 31;
    const int ty = threadIdx.x >> 5;
    const int s0 = blockIdx.x * 32;
    const int c0 = blockIdx.y * 32;
    const int b  = blockIdx.z;

#pragma unroll
    for (int j = 0; j < 4; j++) {
        int c = c0 + ty + j * 8;
        t[tx][ty + j * 8] = inp[((size_t)(b * Cc + c)) * Ss + s0 + tx];
    }
    __syncthreads();
#pragma unroll
    for (int j = 0; j < 4; j++) {
        int s = s0 + ty + j * 8;
        g_inpT[((size_t)b * Ss + s) * Cc + c0 + tx] = t[ty + j * 8][tx];
    }
}

// ---------------------------------------------------------------------------
// Kernel 1: pack weights -> fp16, SW128 tiles, ck' = k*256 + c order
// ---------------------------------------------------------------------------
__global__ __launch_bounds__(256) void wpack_k(const float* __restrict__ w) {
    int t = blockIdx.x * 256 + threadIdx.x;   // 36*8192 threads
    int lane  = t & 31;
    int row   = (t >> 5) & 255;
    int chunk = t >> 13;
    int k  = chunk >> 2;
    int c  = (chunk & 3) * 64 + 2 * lane;

    float wa = w[(size_t)row * CKk + c * 9 + k];
    float wb = w[(size_t)row * CKk + (c + 1) * 9 + k];

    unsigned char* base = g_wA + (size_t)chunk * 32768;
    int off = SWZ(row * 128 + lane * 4);
    *(__half2*)(base + off) = __floats2half2_rn(wa, wb);
}

// ---------------------------------------------------------------------------
// Fused kernel: deformable-gather producer + fp16 mma.sync GEMM
// CTA: M=256, N=128 (one n-tile of 128 pixels), 512 threads, grid (72, 2).
// Smem: A 3-stage (3x32K) | B 2-stage (2x16K) | coords (27.6K)
// ---------------------------------------------------------------------------
#define SM_A     0
#define A_STAGE  32768
#define SM_B     98304
#define B_STAGE  16384
#define SM_CRD   131072
#define SMEM_TOTAL 158720     // 131072 + 1152*24

struct __align__(8) Crd { uint32_t i01, i23; float w00, w01, w10, w11; };

// one producer task: 2 pixels per warp (lanes 0-15 -> px, 16-31 -> px+1),
// each lane gathers 4 channels (float4) for its pixel's 4 bilinear taps.
struct PTask { float4 v00, v01, v10, v11; int px; };

__device__ __forceinline__ PTask prod_issue(const Crd* __restrict__ crd,
                                            const float* __restrict__ bp,
                                            int px_base, int k, int lane) {
    PTask t;
    t.px = px_base + (lane >> 4);
    Crd c = crd[t.px * 9 + k];
    int i00 = c.i01 & 0xffff, i01 = c.i01 >> 16;
    int i10 = c.i23 & 0xffff, i11 = c.i23 >> 16;
    t.v00 = *(const float4*)(bp + (size_t)i00 * Cc);
    t.v01 = *(const float4*)(bp + (size_t)i01 * Cc);
    t.v10 = *(const float4*)(bp + (size_t)i10 * Cc);
    t.v11 = *(const float4*)(bp + (size_t)i11 * Cc);
    return t;
}

__device__ __forceinline__ void prod_complete(const Crd* __restrict__ crd,
                                              const PTask& t, int k, int lane,
                                              unsigned char* __restrict__ bh) {
    Crd c = crd[t.px * 9 + k];
    float v0 = c.w00 * t.v00.x + c.w01 * t.v01.x + c.w10 * t.v10.x + c.w11 * t.v11.x;
    float v1 = c.w00 * t.v00.y + c.w01 * t.v01.y + c.w10 * t.v10.y + c.w11 * t.v11.y;
    float v2 = c.w00 * t.v00.z + c.w01 * t.v01.z + c.w10 * t.v10.z + c.w11 * t.v11.z;
    float v3 = c.w00 * t.v00.w + c.w01 * t.v01.w + c.w10 * t.v10.w + c.w11 * t.v11.w;
    union { __half2 h[2]; uint2 u; } pk;
    pk.h[0] = __floats2half2_rn(v0, v1);
    pk.h[1] = __floats2half2_rn(v2, v3);
    int sw = SWZ(t.px * 128 + (lane & 15) * 8);
    *(uint2*)(bh + sw) = pk.u;
}

__global__ __launch_bounds__(512) void gemm_fused(
    const float* __restrict__ off,    // [B,18,96,96]
    const float* __restrict__ msk,    // [B,9,96,96]
    const float* __restrict__ bias,
    float* __restrict__ out)
{
    extern __shared__ __align__(128) unsigned char smem[];
    const uint32_t sb = smem_u32(smem);

    const int tid  = threadIdx.x;
    const int wid  = tid >> 5;
    const int lane = tid & 31;
    const int n_t  = blockIdx.x;
    const int b    = blockIdx.y;

    Crd* crd = (Crd*)(smem + SM_CRD);
    const float* inpT_b = g_inpT + (size_t)b * Ss * Cc;

    // ---- coordinate/weight setup for this CTA's 128 pixels x 9 taps ----
    for (int r = tid; r < 128 * 9; r += 512) {
        int px = r / 9;
        int k  = r - px * 9;
        int s  = n_t * 128 + px;
        int oh = s / 96;
        int ow = s - oh * 96;

        float dy = off[((size_t)(b * 18 + 2 * k)) * Ss + s];
        float dx = off[((size_t)(b * 18 + 2 * k + 1)) * Ss + s];
        float m  = msk[((size_t)(b * 9 + k)) * Ss + s];

        float y = (float)(oh - 1 + k / 3) + dy;
        float x = (float)(ow - 1 + k % 3) + dx;
        float yf = floorf(y), xf = floorf(x);
        float wy = y - yf,    wx = x - xf;
        int iy = (int)yf, ix = (int)xf;

        float vy0 = (iy >= 0     && iy < 96)     ? 1.0f : 0.0f;
        float vy1 = (iy + 1 >= 0 && iy + 1 < 96) ? 1.0f : 0.0f;
        float vx0 = (ix >= 0     && ix < 96)     ? 1.0f : 0.0f;
        float vx1 = (ix + 1 >= 0 && ix + 1 < 96) ? 1.0f : 0.0f;
        int cy0 = min(max(iy, 0), 95),     cy1 = min(max(iy + 1, 0), 95);
        int cx0 = min(max(ix, 0), 95),     cx1 = min(max(ix + 1, 0), 95);

        Crd c;
        c.i01 = (uint32_t)(cy0 * 96 + cx0) | ((uint32_t)(cy0 * 96 + cx1) << 16);
        c.i23 = (uint32_t)(cy1 * 96 + cx0) | ((uint32_t)(cy1 * 96 + cx1) << 16);
        c.w00 = m * (1.0f - wy) * (1.0f - wx) * vy0 * vx0;
        c.w01 = m * (1.0f - wy) * wx          * vy0 * vx1;
        c.w10 = m * wy * (1.0f - wx)          * vy1 * vx0;
        c.w11 = m * wy * wx                   * vy1 * vx1;
        crd[r] = c;
    }
    __syncthreads();

    // ---- prologue: produce B chunk 0 (stage 0); prefetch A chunks 0,1 ----
    {
        unsigned char* bdst = smem + SM_B;
        const float* bp = inpT_b + (lane & 15) * 4;      // chunk 0: k=0, cg=0
        const int pxb = wid * 8;
#pragma unroll
        for (int e = 0; e < 4; e++) {
            PTask t = prod_issue(crd, bp, pxb + 2 * e, 0, lane);
            prod_complete(crd, t, 0, lane, bdst);
        }
    }
#pragma unroll
    for (int pre = 0; pre < 2; pre++) {
        uint32_t st = sb + SM_A + pre * A_STAGE;
        const unsigned char* a = g_wA + (size_t)pre * 32768;
#pragma unroll
        for (int i = 0; i < 4; i++)
            cp16(st + (tid + i * 512) * 16, a + (tid + i * 512) * 16);
        cp_commit();
    }
    cp_wait<1>();
    __syncthreads();     // A(0) visible; B(0) sealed

    // per-warp MMA tile: 16 warps = 4(m) x 4(n); warp tile 64(m) x 32(n)
    const int wm = (wid & 3) * 64;
    const int wn = (wid >> 2) * 32;

    const int a_r  = (lane & 7) + ((lane >> 3) & 1) * 8;
    const int a_cb = (lane >> 4) * 16;
    const int b_r  = (lane & 7) + (lane >> 4) * 8;
    const int b_cb = ((lane >> 3) & 1) * 16;

    float acc[4][4][4];
#pragma unroll
    for (int i = 0; i < 4; i++)
#pragma unroll
        for (int j = 0; j < 4; j++)
#pragma unroll
            for (int q = 0; q < 4; q++) acc[i][j][q] = 0.0f;

    for (int ch = 0; ch < NCHUNK; ch++) {
        const uint32_t stA = sb + SM_A + (ch % 3) * A_STAGE;
        const uint32_t stB = sb + SM_B + (ch & 1) * B_STAGE;

        // prefetch A(ch+2) into stage (ch+2)%3 (not read this iteration)
        if (ch + 2 < NCHUNK) {
            uint32_t stP = sb + SM_A + ((ch + 2) % 3) * A_STAGE;
            const unsigned char* a = g_wA + (size_t)(ch + 2) * 32768;
#pragma unroll
            for (int i = 0; i < 4; i++)
                cp16(stP + (tid + i * 512) * 16, a + (tid + i * 512) * 16);
        }
        cp_commit();     // uniform group accounting

        // producer state for chunk ch+1 (into the other B stage)
        const bool prod = (ch + 1 < NCHUNK);
        const int pk  = (ch + 1) >> 2;
        const int pcg = (ch + 1) & 3;
        unsigned char* bdst = smem + SM_B + ((ch + 1) & 1) * B_STAGE;
        const float* bp = inpT_b + pcg * 64 + (lane & 15) * 4;
        const int pxb = wid * 8;

        PTask ta, tb;
        if (prod) {
            ta = prod_issue(crd, bp, pxb + 0, pk, lane);
            tb = prod_issue(crd, bp, pxb + 2, pk, lane);
        }

#pragma unroll
        for (int ks = 0; ks < 4; ks++) {
            const int kb = ks * 32;

            uint32_t Bf[2][4];
#pragma unroll
            for (int np = 0; np < 2; np++) {
                int row = wn + np * 16 + b_r;
                uint32_t rel = row * 128 + ((kb + b_cb) ^ ((row & 7) * 16));
                ldm4(Bf[np], stB + rel);
            }

#pragma unroll
            for (int mf = 0; mf < 4; mf++) {
                int row = wm + mf * 16 + a_r;
                uint32_t rel = row * 128 + ((kb + a_cb) ^ ((row & 7) * 16));
                uint32_t Af[4];
                ldm4(Af, stA + rel);
#pragma unroll
                for (int nf = 0; nf < 4; nf++)
                    mma16816(acc[mf][nf], Af,
                             Bf[nf >> 1][(nf & 1) * 2],
                             Bf[nf >> 1][(nf & 1) * 2 + 1]);
            }

            if (prod) {
                prod_complete(crd, ta, pk, lane, bdst);
                ta = tb;
                if (ks < 2)
                    tb = prod_issue(crd, bp, pxb + 2 * (ks + 2), pk, lane);
            }
        }

        cp_wait<1>();      // A(ch+1) complete (this thread)
        __syncthreads();   // A(ch+1) visible to all; B(ch+1) sealed
    }

    // ---- epilogue ----
    const int mrow = lane >> 2;
    const int ncol = (lane & 3) * 2;
#pragma unroll
    for (int mf = 0; mf < 4; mf++) {
        int m0 = wm + mf * 16 + mrow;
        float bv0 = __ldg(bias + m0);
        float bv8 = __ldg(bias + m0 + 8);
        float* r0 = out + ((size_t)(b * Oo + m0)) * Ss + n_t * 128;
        float* r8 = r0 + (size_t)8 * Ss;
#pragma unroll
        for (int nf = 0; nf < 4; nf++) {
            int n = wn + nf * 8 + ncol;
            float2 v0, v8;
            v0.x = acc[mf][nf][0] + bv0;  v0.y = acc[mf][nf][1] + bv0;
            v8.x = acc[mf][nf][2] + bv8;  v8.y = acc[mf][nf][3] + bv8;
            *(float2*)(r0 + n) = v0;
            *(float2*)(r8 + n) = v8;
        }
    }
}

// ---------------------------------------------------------------------------
extern "C" void kernel_launch(void* const* d_in, const int* in_sizes, int n_in,
                              void* d_out, int out_size)
{
    const float* inp  = (const float*)d_in[0];
    const float* off  = (const float*)d_in[1];
    const float* msk  = (const float*)d_in[2];
    const float* wt   = (const float*)d_in[3];
    const float* bias = (const float*)d_in[4];
    float* out = (float*)d_out;

    cudaFuncSetAttribute(gemm_fused, cudaFuncAttributeMaxDynamicSharedMemorySize,
                         SMEM_TOTAL);

    {
        dim3 g(Ss / 32, Cc / 32, Bz);      // (288, 8, 2)
        transpose_k<<<g, 256>>>(inp);
    }
    wpack_k<<<(NCHUNK * 8192) / 256, 256>>>(wt);
    {
        dim3 g(NTILE, Bz);                 // (72, 2)
        gemm_fused<<<g, 512, SMEM_TOTAL>>>(off, msk, bias, out);
    }
}

// round 7
// speedup vs baseline: 7.2605x; 1.3333x over previous
#include <cuda_runtime.h>
#include <cuda_fp16.h>
#include <cstdint>

// ---------------------------------------------------------------------------
// Problem constants
// ---------------------------------------------------------------------------
#define Bz   2
#define Cc   256
#define Oo   256
#define Ss   9216          // 96*96
#define CKk  2304          // 256*9
#define NCHUNK 36          // 2304 / 64 (K per chunk = 64); ck' = k*256 + c
#define NTILE  72          // 9216 / 128 (pixels per GEMM tile = 128)

// Transposed input: [B][HW][C] fp16
__device__ __half g_inpT[(size_t)Bz * Ss * Cc];
// Packed weights: [chunk][256 rows x 64 fp16, SW128] = 32KB per chunk
__device__ __align__(1024) unsigned char g_wA[(size_t)NCHUNK * 32768];

#define SWZ(o) ((o) ^ (((o) >> 3) & 0x70))

__device__ __forceinline__ uint32_t smem_u32(const void* p) {
    uint32_t a;
    asm("{ .reg .u64 t; cvta.to.shared.u64 t, %1; cvt.u32.u64 %0, t; }"
        : "=r"(a) : "l"(p));
    return a;
}

// ---- portable async-copy + tensor-core helpers (NO sm_103a-only features) --
__device__ __forceinline__ void cp16(uint32_t dst, const void* src) {
    asm volatile("cp.async.cg.shared.global [%0], [%1], 16;"
                 :: "r"(dst), "l"(src) : "memory");
}
__device__ __forceinline__ void cp_commit() {
    asm volatile("cp.async.commit_group;" ::: "memory");
}
template <int N>
__device__ __forceinline__ void cp_wait() {
    asm volatile("cp.async.wait_group %0;" :: "n"(N) : "memory");
}
__device__ __forceinline__ void ldm4(uint32_t* r, uint32_t addr) {
    asm volatile("ldmatrix.sync.aligned.m8n8.x4.shared.b16 {%0,%1,%2,%3}, [%4];"
                 : "=r"(r[0]), "=r"(r[1]), "=r"(r[2]), "=r"(r[3]) : "r"(addr));
}
__device__ __forceinline__ void mma16816(float* d, const uint32_t* a,
                                         uint32_t b0, uint32_t b1) {
    asm volatile(
        "mma.sync.aligned.m16n8k16.row.col.f32.f16.f16.f32 "
        "{%0,%1,%2,%3}, {%4,%5,%6,%7}, {%8,%9}, {%0,%1,%2,%3};"
        : "+f"(d[0]), "+f"(d[1]), "+f"(d[2]), "+f"(d[3])
        : "r"(a[0]), "r"(a[1]), "r"(a[2]), "r"(a[3]), "r"(b0), "r"(b1));
}

// ---------------------------------------------------------------------------
// Kernel 0: transpose input [B][C][HW] fp32 -> [B][HW][C] fp16
// ---------------------------------------------------------------------------
__global__ __launch_bounds__(256) void transpose_k(const float* __restrict__ inp) {
    __shared__ float t[32][33];
    const int tx = threadIdx.x & 31;
    const int ty = threadIdx.x >> 5;
    const int s0 = blockIdx.x * 32;
    const int c0 = blockIdx.y * 32;
    const int b  = blockIdx.z;

#pragma unroll
    for (int j = 0; j < 4; j++) {
        int c = c0 + ty + j * 8;
        t[tx][ty + j * 8] = inp[((size_t)(b * Cc + c)) * Ss + s0 + tx];
    }
    __syncthreads();
#pragma unroll
    for (int j = 0; j < 4; j++) {
        int s = s0 + ty + j * 8;
        g_inpT[((size_t)b * Ss + s) * Cc + c0 + tx] = __float2half_rn(t[ty + j * 8][tx]);
    }
}

// ---------------------------------------------------------------------------
// Kernel 1: pack weights -> fp16, SW128 tiles, ck' = k*256 + c order
// ---------------------------------------------------------------------------
__global__ __launch_bounds__(256) void wpack_k(const float* __restrict__ w) {
    int t = blockIdx.x * 256 + threadIdx.x;   // 36*8192 threads
    int lane  = t & 31;
    int row   = (t >> 5) & 255;
    int chunk = t >> 13;
    int k  = chunk >> 2;
    int c  = (chunk & 3) * 64 + 2 * lane;

    float wa = w[(size_t)row * CKk + c * 9 + k];
    float wb = w[(size_t)row * CKk + (c + 1) * 9 + k];

    unsigned char* base = g_wA + (size_t)chunk * 32768;
    int off = SWZ(row * 128 + lane * 4);
    *(__half2*)(base + off) = __floats2half2_rn(wa, wb);
}

// ---------------------------------------------------------------------------
// Fused kernel: deformable-gather producer + fp16 mma.sync GEMM
// CTA: M=256, N=128 (one n-tile of 128 pixels), 512 threads, grid (72, 2).
// Smem: A 3-stage (3x32K) | B 2-stage (2x16K) | coords (27.6K)
// Producer: per issue a warp covers 4 px x 64 ch (8 lanes/px, 8 ch/lane,
// uint4 fp16 gathers) -> 2 issues per warp per chunk.
// ---------------------------------------------------------------------------
#define SM_A     0
#define A_STAGE  32768
#define SM_B     98304
#define B_STAGE  16384
#define SM_CRD   131072
#define SMEM_TOTAL 158720     // 131072 + 1152*24

struct __align__(8) Crd { uint32_t i01, i23; float w00, w01, w10, w11; };

struct PTask { uint4 v00, v01, v10, v11; int px; };

__device__ __forceinline__ PTask prod_issue(const Crd* __restrict__ crd,
                                            const __half* __restrict__ bp,
                                            int px_base, int k, int lane) {
    PTask t;
    t.px = px_base + (lane >> 3);
    Crd c = crd[t.px * 9 + k];
    int i00 = c.i01 & 0xffff, i01 = c.i01 >> 16;
    int i10 = c.i23 & 0xffff, i11 = c.i23 >> 16;
    t.v00 = *(const uint4*)(bp + (size_t)i00 * Cc);
    t.v01 = *(const uint4*)(bp + (size_t)i01 * Cc);
    t.v10 = *(const uint4*)(bp + (size_t)i10 * Cc);
    t.v11 = *(const uint4*)(bp + (size_t)i11 * Cc);
    return t;
}

__device__ __forceinline__ void prod_complete(const Crd* __restrict__ crd,
                                              const PTask& t, int k, int lane,
                                              unsigned char* __restrict__ bh) {
    Crd c = crd[t.px * 9 + k];
    union { uint4 u; __half2 h[4]; } x00, x01, x10, x11, pk;
    x00.u = t.v00; x01.u = t.v01; x10.u = t.v10; x11.u = t.v11;
#pragma unroll
    for (int j = 0; j < 4; j++) {
        float2 a = __half22float2(x00.h[j]);
        float2 d = __half22float2(x01.h[j]);
        float2 e = __half22float2(x10.h[j]);
        float2 f = __half22float2(x11.h[j]);
        float r0 = c.w00 * a.x + c.w01 * d.x + c.w10 * e.x + c.w11 * f.x;
        float r1 = c.w00 * a.y + c.w01 * d.y + c.w10 * e.y + c.w11 * f.y;
        pk.h[j] = __floats2half2_rn(r0, r1);
    }
    int sw = SWZ(t.px * 128 + (lane & 7) * 16);
    *(uint4*)(bh + sw) = pk.u;
}

__global__ __launch_bounds__(512) void gemm_fused(
    const float* __restrict__ off,    // [B,18,96,96]
    const float* __restrict__ msk,    // [B,9,96,96]
    const float* __restrict__ bias,
    float* __restrict__ out)
{
    extern __shared__ __align__(128) unsigned char smem[];
    const uint32_t sb = smem_u32(smem);

    const int tid  = threadIdx.x;
    const int wid  = tid >> 5;
    const int lane = tid & 31;
    const int n_t  = blockIdx.x;
    const int b    = blockIdx.y;

    Crd* crd = (Crd*)(smem + SM_CRD);
    const __half* inpT_b = g_inpT + (size_t)b * Ss * Cc;

    // ---- coordinate/weight setup for this CTA's 128 pixels x 9 taps ----
    for (int r = tid; r < 128 * 9; r += 512) {
        int px = r / 9;
        int k  = r - px * 9;
        int s  = n_t * 128 + px;
        int oh = s / 96;
        int ow = s - oh * 96;

        float dy = off[((size_t)(b * 18 + 2 * k)) * Ss + s];
        float dx = off[((size_t)(b * 18 + 2 * k + 1)) * Ss + s];
        float m  = msk[((size_t)(b * 9 + k)) * Ss + s];

        float y = (float)(oh - 1 + k / 3) + dy;
        float x = (float)(ow - 1 + k % 3) + dx;
        float yf = floorf(y), xf = floorf(x);
        float wy = y - yf,    wx = x - xf;
        int iy = (int)yf, ix = (int)xf;

        float vy0 = (iy >= 0     && iy < 96)     ? 1.0f : 0.0f;
        float vy1 = (iy + 1 >= 0 && iy + 1 < 96) ? 1.0f : 0.0f;
        float vx0 = (ix >= 0     && ix < 96)     ? 1.0f : 0.0f;
        float vx1 = (ix + 1 >= 0 && ix + 1 < 96) ? 1.0f : 0.0f;
        int cy0 = min(max(iy, 0), 95),     cy1 = min(max(iy + 1, 0), 95);
        int cx0 = min(max(ix, 0), 95),     cx1 = min(max(ix + 1, 0), 95);

        Crd c;
        c.i01 = (uint32_t)(cy0 * 96 + cx0) | ((uint32_t)(cy0 * 96 + cx1) << 16);
        c.i23 = (uint32_t)(cy1 * 96 + cx0) | ((uint32_t)(cy1 * 96 + cx1) << 16);
        c.w00 = m * (1.0f - wy) * (1.0f - wx) * vy0 * vx0;
        c.w01 = m * (1.0f - wy) * wx          * vy0 * vx1;
        c.w10 = m * wy * (1.0f - wx)          * vy1 * vx0;
        c.w11 = m * wy * wx                   * vy1 * vx1;
        crd[r] = c;
    }
    __syncthreads();

    // ---- prologue: produce B chunk 0 (stage 0); prefetch A chunks 0,1 ----
    {
        unsigned char* bdst = smem + SM_B;
        const __half* bp = inpT_b + (lane & 7) * 8;     // chunk 0: k=0, cg=0
        const int pxb = wid * 8;
#pragma unroll
        for (int e = 0; e < 2; e++) {
            PTask t = prod_issue(crd, bp, pxb + 4 * e, 0, lane);
            prod_complete(crd, t, 0, lane, bdst);
        }
    }
#pragma unroll
    for (int pre = 0; pre < 2; pre++) {
        uint32_t st = sb + SM_A + pre * A_STAGE;
        const unsigned char* a = g_wA + (size_t)pre * 32768;
#pragma unroll
        for (int i = 0; i < 4; i++)
            cp16(st + (tid + i * 512) * 16, a + (tid + i * 512) * 16);
        cp_commit();
    }
    cp_wait<1>();
    __syncthreads();     // A(0) visible; B(0) sealed

    // per-warp MMA tile: 16 warps = 4(m) x 4(n); warp tile 64(m) x 32(n)
    const int wm = (wid & 3) * 64;
    const int wn = (wid >> 2) * 32;

    const int a_r  = (lane & 7) + ((lane >> 3) & 1) * 8;
    const int a_cb = (lane >> 4) * 16;
    const int b_r  = (lane & 7) + (lane >> 4) * 8;
    const int b_cb = ((lane >> 3) & 1) * 16;

    float acc[4][4][4];
#pragma unroll
    for (int i = 0; i < 4; i++)
#pragma unroll
        for (int j = 0; j < 4; j++)
#pragma unroll
            for (int q = 0; q < 4; q++) acc[i][j][q] = 0.0f;

    for (int ch = 0; ch < NCHUNK; ch++) {
        const uint32_t stA = sb + SM_A + (ch % 3) * A_STAGE;
        const uint32_t stB = sb + SM_B + (ch & 1) * B_STAGE;

        // prefetch A(ch+2) into stage (ch+2)%3 (not read this iteration)
        if (ch + 2 < NCHUNK) {
            uint32_t stP = sb + SM_A + ((ch + 2) % 3) * A_STAGE;
            const unsigned char* a = g_wA + (size_t)(ch + 2) * 32768;
#pragma unroll
            for (int i = 0; i < 4; i++)
                cp16(stP + (tid + i * 512) * 16, a + (tid + i * 512) * 16);
        }
        cp_commit();     // uniform group accounting

        // producer state for chunk ch+1 (into the other B stage)
        const bool prod = (ch + 1 < NCHUNK);
        const int pk  = (ch + 1) >> 2;
        const int pcg = (ch + 1) & 3;
        unsigned char* bdst = smem + SM_B + ((ch + 1) & 1) * B_STAGE;
        const __half* bp = inpT_b + pcg * 64 + (lane & 7) * 8;
        const int pxb = wid * 8;

        PTask ta, tb;
        if (prod) {
            ta = prod_issue(crd, bp, pxb + 0, pk, lane);
            tb = prod_issue(crd, bp, pxb + 4, pk, lane);
        }

#pragma unroll
        for (int ks = 0; ks < 4; ks++) {
            const int kb = ks * 32;

            uint32_t Bf[2][4];
#pragma unroll
            for (int np = 0; np < 2; np++) {
                int row = wn + np * 16 + b_r;
                uint32_t rel = row * 128 + ((kb + b_cb) ^ ((row & 7) * 16));
                ldm4(Bf[np], stB + rel);
            }

#pragma unroll
            for (int mf = 0; mf < 4; mf++) {
                int row = wm + mf * 16 + a_r;
                uint32_t rel = row * 128 + ((kb + a_cb) ^ ((row & 7) * 16));
                uint32_t Af[4];
                ldm4(Af, stA + rel);
#pragma unroll
                for (int nf = 0; nf < 4; nf++)
                    mma16816(acc[mf][nf], Af,
                             Bf[nf >> 1][(nf & 1) * 2],
                             Bf[nf >> 1][(nf & 1) * 2 + 1]);
            }

            if (prod) {
                if (ks == 1) prod_complete(crd, ta, pk, lane, bdst);
                if (ks == 3) prod_complete(crd, tb, pk, lane, bdst);
            }
        }

        cp_wait<1>();      // A(ch+1) complete (this thread)
        __syncthreads();   // A(ch+1) visible to all; B(ch+1) sealed
    }

    // ---- epilogue ----
    const int mrow = lane >> 2;
    const int ncol = (lane & 3) * 2;
#pragma unroll
    for (int mf = 0; mf < 4; mf++) {
        int m0 = wm + mf * 16 + mrow;
        float bv0 = __ldg(bias + m0);
        float bv8 = __ldg(bias + m0 + 8);
        float* r0 = out + ((size_t)(b * Oo + m0)) * Ss + n_t * 128;
        float* r8 = r0 + (size_t)8 * Ss;
#pragma unroll
        for (int nf = 0; nf < 4; nf++) {
            int n = wn + nf * 8 + ncol;
            float2 v0, v8;
            v0.x = acc[mf][nf][0] + bv0;  v0.y = acc[mf][nf][1] + bv0;
            v8.x = acc[mf][nf][2] + bv8;  v8.y = acc[mf][nf][3] + bv8;
            *(float2*)(r0 + n) = v0;
            *(float2*)(r8 + n) = v8;
        }
    }
}

// ---------------------------------------------------------------------------
extern "C" void kernel_launch(void* const* d_in, const int* in_sizes, int n_in,
                              void* d_out, int out_size)
{
    const float* inp  = (const float*)d_in[0];
    const float* off  = (const float*)d_in[1];
    const float* msk  = (const float*)d_in[2];
    const float* wt   = (const float*)d_in[3];
    const float* bias = (const float*)d_in[4];
    float* out = (float*)d_out;

    cudaFuncSetAttribute(gemm_fused, cudaFuncAttributeMaxDynamicSharedMemorySize,
                         SMEM_TOTAL);

    {
        dim3 g(Ss / 32, Cc / 32, Bz);      // (288, 8, 2)
        transpose_k<<<g, 256>>>(inp);
    }
    wpack_k<<<(NCHUNK * 8192) / 256, 256>>>(wt);
    {
        dim3 g(NTILE, Bz);                 // (72, 2)
        gemm_fused<<<g, 512, SMEM_TOTAL>>>(off, msk, bias, out);
    }
}

// round 8
// speedup vs baseline: 7.5564x; 1.0408x over previous
#include <cuda_runtime.h>
#include <cuda_fp16.h>
#include <cstdint>

// ---------------------------------------------------------------------------
// Problem constants
// ---------------------------------------------------------------------------
#define Bz   2
#define Cc   256
#define Oo   256
#define Ss   9216          // 96*96
#define CKk  2304          // 256*9
#define NCHUNK 36          // K chunks of 64; ck' = k*256 + c
#define NSUPER 18          // merged iterations (K=128 each)
#define NTILE  72          // 9216 / 128 pixels per GEMM tile

// Transposed input: [B][HW][C] fp16
__device__ __half g_inpT[(size_t)Bz * Ss * Cc];
// Packed weights: [chunk][256 rows x 64 fp16, SW128] = 32KB per chunk
__device__ __align__(1024) unsigned char g_wA[(size_t)NCHUNK * 32768];

#define SWZ(o) ((o) ^ (((o) >> 3) & 0x70))

__device__ __forceinline__ uint32_t smem_u32(const void* p) {
    uint32_t a;
    asm("{ .reg .u64 t; cvta.to.shared.u64 t, %1; cvt.u32.u64 %0, t; }"
        : "=r"(a) : "l"(p));
    return a;
}

// ---- portable async-copy + tensor-core helpers (NO sm_103a-only features) --
__device__ __forceinline__ void cp16(uint32_t dst, const void* src) {
    asm volatile("cp.async.cg.shared.global [%0], [%1], 16;"
                 :: "r"(dst), "l"(src) : "memory");
}
__device__ __forceinline__ void cp_commit() {
    asm volatile("cp.async.commit_group;" ::: "memory");
}
template <int N>
__device__ __forceinline__ void cp_wait() {
    asm volatile("cp.async.wait_group %0;" :: "n"(N) : "memory");
}
__device__ __forceinline__ void ldm4(uint32_t* r, uint32_t addr) {
    asm volatile("ldmatrix.sync.aligned.m8n8.x4.shared.b16 {%0,%1,%2,%3}, [%4];"
                 : "=r"(r[0]), "=r"(r[1]), "=r"(r[2]), "=r"(r[3]) : "r"(addr));
}
__device__ __forceinline__ void mma16816(float* d, const uint32_t* a,
                                         uint32_t b0, uint32_t b1) {
    asm volatile(
        "mma.sync.aligned.m16n8k16.row.col.f32.f16.f16.f32 "
        "{%0,%1,%2,%3}, {%4,%5,%6,%7}, {%8,%9}, {%0,%1,%2,%3};"
        : "+f"(d[0]), "+f"(d[1]), "+f"(d[2]), "+f"(d[3])
        : "r"(a[0]), "r"(a[1]), "r"(a[2]), "r"(a[3]), "r"(b0), "r"(b1));
}

// ---------------------------------------------------------------------------
// Kernel 0: transpose input [B][C][HW] fp32 -> [B][HW][C] fp16
// 32(s) x 64(c) tiles; half2 stores (128B per warp wavefront)
// ---------------------------------------------------------------------------
__global__ __launch_bounds__(256) void transpose_k(const float* __restrict__ inp) {
    __shared__ float t[32][65];
    const int tx = threadIdx.x & 31;
    const int ty = threadIdx.x >> 5;       // 0..7
    const int s0 = blockIdx.x * 32;        // 288
    const int c0 = blockIdx.y * 64;        // 4
    const int b  = blockIdx.z;

#pragma unroll
    for (int j = 0; j < 8; j++) {
        int cl = ty + j * 8;
        t[tx][cl] = inp[((size_t)(b * Cc + c0 + cl)) * Ss + s0 + tx];
    }
    __syncthreads();
#pragma unroll
    for (int j = 0; j < 4; j++) {
        int sl = ty + j * 8;
        __half2 h = __floats2half2_rn(t[sl][2 * tx], t[sl][2 * tx + 1]);
        *(__half2*)&g_inpT[((size_t)b * Ss + s0 + sl) * Cc + c0 + 2 * tx] = h;
    }
}

// ---------------------------------------------------------------------------
// Kernel 1: pack weights -> fp16, SW128 tiles, ck' = k*256 + c order
// ---------------------------------------------------------------------------
__global__ __launch_bounds__(256) void wpack_k(const float* __restrict__ w) {
    int t = blockIdx.x * 256 + threadIdx.x;   // 36*8192 threads
    int lane  = t & 31;
    int row   = (t >> 5) & 255;
    int chunk = t >> 13;
    int k  = chunk >> 2;
    int c  = (chunk & 3) * 64 + 2 * lane;

    float wa = w[(size_t)row * CKk + c * 9 + k];
    float wb = w[(size_t)row * CKk + (c + 1) * 9 + k];

    unsigned char* base = g_wA + (size_t)chunk * 32768;
    int off = SWZ(row * 128 + lane * 4);
    *(__half2*)(base + off) = __floats2half2_rn(wa, wb);
}

// ---------------------------------------------------------------------------
// Fused kernel: deformable-gather producer + fp16 mma.sync GEMM
// CTA: M=256, N=128, 512 threads, grid (72, 2). K=128 per iteration (18 iters).
// Smem: A 2-stage (2x64K) | B 2-stage (2x32K) | coords (27.6K) = 224256
// ---------------------------------------------------------------------------
#define SM_A     0
#define A_STAGE  65536
#define SM_B     131072
#define B_STAGE  32768
#define SM_CRD   196608
#define SMEM_TOTAL 224256

struct __align__(8) Crd { uint32_t i01, i23; float w00, w01, w10, w11; };

struct PTask { uint4 v00, v01, v10, v11; int px; };

__device__ __forceinline__ PTask prod_issue(const Crd* __restrict__ crd,
                                            const __half* __restrict__ bp,
                                            int px_base, int k, int lane) {
    PTask t;
    t.px = px_base + (lane >> 3);
    Crd c = crd[t.px * 9 + k];
    int i00 = c.i01 & 0xffff, i01 = c.i01 >> 16;
    int i10 = c.i23 & 0xffff, i11 = c.i23 >> 16;
    t.v00 = *(const uint4*)(bp + (size_t)i00 * Cc);
    t.v01 = *(const uint4*)(bp + (size_t)i01 * Cc);
    t.v10 = *(const uint4*)(bp + (size_t)i10 * Cc);
    t.v11 = *(const uint4*)(bp + (size_t)i11 * Cc);
    return t;
}

__device__ __forceinline__ void prod_complete(const Crd* __restrict__ crd,
                                              const PTask& t, int k, int lane,
                                              unsigned char* __restrict__ bh) {
    Crd c = crd[t.px * 9 + k];
    union { uint4 u; __half2 h[4]; } x00, x01, x10, x11, pk;
    x00.u = t.v00; x01.u = t.v01; x10.u = t.v10; x11.u = t.v11;
#pragma unroll
    for (int j = 0; j < 4; j++) {
        float2 a = __half22float2(x00.h[j]);
        float2 d = __half22float2(x01.h[j]);
        float2 e = __half22float2(x10.h[j]);
        float2 f = __half22float2(x11.h[j]);
        float r0 = c.w00 * a.x + c.w01 * d.x + c.w10 * e.x + c.w11 * f.x;
        float r1 = c.w00 * a.y + c.w01 * d.y + c.w10 * e.y + c.w11 * f.y;
        pk.h[j] = __floats2half2_rn(r0, r1);
    }
    int sw = SWZ(t.px * 128 + (lane & 7) * 16);
    *(uint4*)(bh + sw) = pk.u;
}

__global__ __launch_bounds__(512) void gemm_fused(
    const float* __restrict__ off,    // [B,18,96,96]
    const float* __restrict__ msk,    // [B,9,96,96]
    const float* __restrict__ bias,
    float* __restrict__ out)
{
    extern __shared__ __align__(128) unsigned char smem[];
    const uint32_t sb = smem_u32(smem);

    const int tid  = threadIdx.x;
    const int wid  = tid >> 5;
    const int lane = tid & 31;
    const int n_t  = blockIdx.x;
    const int b    = blockIdx.y;

    Crd* crd = (Crd*)(smem + SM_CRD);
    const __half* inpT_b = g_inpT + (size_t)b * Ss * Cc;

    // ---- coordinate/weight setup for this CTA's 128 pixels x 9 taps ----
    for (int r = tid; r < 128 * 9; r += 512) {
        int px = r / 9;
        int k  = r - px * 9;
        int s  = n_t * 128 + px;
        int oh = s / 96;
        int ow = s - oh * 96;

        float dy = off[((size_t)(b * 18 + 2 * k)) * Ss + s];
        float dx = off[((size_t)(b * 18 + 2 * k + 1)) * Ss + s];
        float m  = msk[((size_t)(b * 9 + k)) * Ss + s];

        float y = (float)(oh - 1 + k / 3) + dy;
        float x = (float)(ow - 1 + k % 3) + dx;
        float yf = floorf(y), xf = floorf(x);
        float wy = y - yf,    wx = x - xf;
        int iy = (int)yf, ix = (int)xf;

        float vy0 = (iy >= 0     && iy < 96)     ? 1.0f : 0.0f;
        float vy1 = (iy + 1 >= 0 && iy + 1 < 96) ? 1.0f : 0.0f;
        float vx0 = (ix >= 0     && ix < 96)     ? 1.0f : 0.0f;
        float vx1 = (ix + 1 >= 0 && ix + 1 < 96) ? 1.0f : 0.0f;
        int cy0 = min(max(iy, 0), 95),     cy1 = min(max(iy + 1, 0), 95);
        int cx0 = min(max(ix, 0), 95),     cx1 = min(max(ix + 1, 0), 95);

        Crd c;
        c.i01 = (uint32_t)(cy0 * 96 + cx0) | ((uint32_t)(cy0 * 96 + cx1) << 16);
        c.i23 = (uint32_t)(cy1 * 96 + cx0) | ((uint32_t)(cy1 * 96 + cx1) << 16);
        c.w00 = m * (1.0f - wy) * (1.0f - wx) * vy0 * vx0;
        c.w01 = m * (1.0f - wy) * wx          * vy0 * vx1;
        c.w10 = m * wy * (1.0f - wx)          * vy1 * vx0;
        c.w11 = m * wy * wx                   * vy1 * vx1;
        crd[r] = c;
    }
    __syncthreads();

    // ---- prologue: produce B chunks 0,1 into stage 0; prefetch A super 0 ----
    {
        const int pxb = wid * 8;
#pragma unroll
        for (int c = 0; c < 2; c++) {
            unsigned char* bdst = smem + SM_B + c * 16384;
            const __half* bp = inpT_b + c * 64 + (lane & 7) * 8;  // pk=0, pcg=c
#pragma unroll
            for (int e = 0; e < 2; e++) {
                PTask t = prod_issue(crd, bp, pxb + 4 * e, 0, lane);
                prod_complete(crd, t, 0, lane, bdst);
            }
        }
    }
    {
        uint32_t st = sb + SM_A;
        const unsigned char* a = g_wA;
#pragma unroll
        for (int i = 0; i < 8; i++)
            cp16(st + (tid + i * 512) * 16, a + (tid + i * 512) * 16);
        cp_commit();
    }
    cp_wait<0>();
    __syncthreads();     // A(0) visible; B super 0 sealed

    // per-warp MMA tile: 16 warps = 4(m) x 4(n); warp tile 64(m) x 32(n)
    const int wm = (wid & 3) * 64;
    const int wn = (wid >> 2) * 32;

    const int a_r  = (lane & 7) + ((lane >> 3) & 1) * 8;
    const int a_cb = (lane >> 4) * 16;
    const int b_r  = (lane & 7) + (lane >> 4) * 8;
    const int b_cb = ((lane >> 3) & 1) * 16;

    float acc[4][4][4];
#pragma unroll
    for (int i = 0; i < 4; i++)
#pragma unroll
        for (int j = 0; j < 4; j++)
#pragma unroll
            for (int q = 0; q < 4; q++) acc[i][j][q] = 0.0f;

    for (int it = 0; it < NSUPER; it++) {
        const uint32_t stA = sb + SM_A + (it & 1) * A_STAGE;
        const uint32_t stB = sb + SM_B + (it & 1) * B_STAGE;

        // prefetch A super (it+1) into the other stage (consumed in it-1)
        if (it + 1 < NSUPER) {
            uint32_t stP = sb + SM_A + ((it + 1) & 1) * A_STAGE;
            const unsigned char* a = g_wA + (size_t)(it + 1) * 65536;
#pragma unroll
            for (int i = 0; i < 8; i++)
                cp16(stP + (tid + i * 512) * 16, a + (tid + i * 512) * 16);
        }
        cp_commit();

        // producer for super (it+1): chunks c0p = 2it+2, c1p = 2it+3
        const bool prod = (it + 1 < NSUPER);
        const int c0p = 2 * it + 2;
        const int c1p = 2 * it + 3;
        const int pk0 = c0p >> 2, pk1 = c1p >> 2;
        unsigned char* bd0 = smem + SM_B + ((it + 1) & 1) * B_STAGE;
        unsigned char* bd1 = bd0 + 16384;
        const __half* bp0 = inpT_b + (c0p & 3) * 64 + (lane & 7) * 8;
        const __half* bp1 = inpT_b + (c1p & 3) * 64 + (lane & 7) * 8;
        const int pxb = wid * 8;

        PTask ta, tb;
        if (prod) {
            ta = prod_issue(crd, bp0, pxb + 0, pk0, lane);
            tb = prod_issue(crd, bp0, pxb + 4, pk0, lane);
        }

#pragma unroll
        for (int ks = 0; ks < 8; ks++) {
            const int half_off = (ks >> 2);          // chunk half within super
            const int kb = (ks & 3) * 32;
            const uint32_t bB = stB + half_off * 16384;
            const uint32_t bA = stA + half_off * 32768;

            uint32_t Bf[2][4];
#pragma unroll
            for (int np = 0; np < 2; np++) {
                int row = wn + np * 16 + b_r;
                uint32_t rel = row * 128 + ((kb + b_cb) ^ ((row & 7) * 16));
                ldm4(Bf[np], bB + rel);
            }

#pragma unroll
            for (int mf = 0; mf < 4; mf++) {
                int row = wm + mf * 16 + a_r;
                uint32_t rel = row * 128 + ((kb + a_cb) ^ ((row & 7) * 16));
                uint32_t Af[4];
                ldm4(Af, bA + rel);
#pragma unroll
                for (int nf = 0; nf < 4; nf++)
                    mma16816(acc[mf][nf], Af,
                             Bf[nf >> 1][(nf & 1) * 2],
                             Bf[nf >> 1][(nf & 1) * 2 + 1]);
            }

            if (prod) {
                if (ks == 1) prod_complete(crd, ta, pk0, lane, bd0);
                if (ks == 2) ta = prod_issue(crd, bp1, pxb + 0, pk1, lane);
                if (ks == 3) prod_complete(crd, tb, pk0, lane, bd0);
                if (ks == 4) tb = prod_issue(crd, bp1, pxb + 4, pk1, lane);
                if (ks == 5) prod_complete(crd, ta, pk1, lane, bd1);
                if (ks == 7) prod_complete(crd, tb, pk1, lane, bd1);
            }
        }

        cp_wait<0>();      // A(it+1) complete (this thread)
        __syncthreads();   // A(it+1) + B super (it+1) visible to all
    }

    // ---- epilogue ----
    const int mrow = lane >> 2;
    const int ncol = (lane & 3) * 2;
#pragma unroll
    for (int mf = 0; mf < 4; mf++) {
        int m0 = wm + mf * 16 + mrow;
        float bv0 = __ldg(bias + m0);
        float bv8 = __ldg(bias + m0 + 8);
        float* r0 = out + ((size_t)(b * Oo + m0)) * Ss + n_t * 128;
        float* r8 = r0 + (size_t)8 * Ss;
#pragma unroll
        for (int nf = 0; nf < 4; nf++) {
            int n = wn + nf * 8 + ncol;
            float2 v0, v8;
            v0.x = acc[mf][nf][0] + bv0;  v0.y = acc[mf][nf][1] + bv0;
            v8.x = acc[mf][nf][2] + bv8;  v8.y = acc[mf][nf][3] + bv8;
            *(float2*)(r0 + n) = v0;
            *(float2*)(r8 + n) = v8;
        }
    }
}

// ---------------------------------------------------------------------------
extern "C" void kernel_launch(void* const* d_in, const int* in_sizes, int n_in,
                              void* d_out, int out_size)
{
    const float* inp  = (const float*)d_in[0];
    const float* off  = (const float*)d_in[1];
    const float* msk  = (const float*)d_in[2];
    const float* wt   = (const float*)d_in[3];
    const float* bias = (const float*)d_in[4];
    float* out = (float*)d_out;

    cudaFuncSetAttribute(gemm_fused, cudaFuncAttributeMaxDynamicSharedMemorySize,
                         SMEM_TOTAL);

    {
        dim3 g(Ss / 32, Cc / 64, Bz);      // (288, 4, 2)
        transpose_k<<<g, 256>>>(inp);
    }
    wpack_k<<<(NCHUNK * 8192) / 256, 256>>>(wt);
    {
        dim3 g(NTILE, Bz);                 // (72, 2)
        gemm_fused<<<g, 512, SMEM_TOTAL>>>(off, msk, bias, out);
    }
}